// round 3
// baseline (speedup 1.0000x reference)
#include <cuda_runtime.h>
#include <cuda_fp16.h>

#define G_N   8192
#define NH    8
#define HDIM  64
#define AD    512
#define GFDIM 32
#define CIMG  256
#define IMG   64
#define NPIX  (IMG*IMG)
#define KPTS  12
#define SIGC  9.21f

// Scratch: kv maps in fp16, interleaved [h][pix][k0..63 | v0..63]  (8 MB, L2-resident)
__device__ __half g_kv[NH * NPIX * 128];

__constant__ float c_fix[18] = {0,0,0, 1,0,0, 0,1,0, 0,0,1, -1,0,0, 0,-1,0};

// ---------------------------------------------------------------------------
// Kernel A: kmap/vmap = Wk/Wv @ image_features -> fp16 interleaved g_kv.
//   M=4096 pixels, N=512, K=256. Tile 64x128, TK=16, thread tile 4x8 per map.
// ---------------------------------------------------------------------------
__global__ __launch_bounds__(256) void kv_gemm(
    const float* __restrict__ img, const float* __restrict__ Wk,
    const float* __restrict__ Wv)
{
    const int m0 = blockIdx.x * 64;
    const int n0 = blockIdx.y * 128;
    __shared__ float As[16][64];
    __shared__ float Bks[16][128];
    __shared__ float Bvs[16][128];
    const int t  = threadIdx.x;
    const int tx = t & 15, ty = t >> 4;

    float ak[4][8], av[4][8];
#pragma unroll
    for (int i = 0; i < 4; i++)
#pragma unroll
        for (int j = 0; j < 8; j++) { ak[i][j] = 0.f; av[i][j] = 0.f; }

    for (int c0 = 0; c0 < CIMG; c0 += 16) {
        *(float4*)&As[ty][tx * 4] =
            *(const float4*)(img + (size_t)(c0 + ty) * NPIX + m0 + tx * 4);
#pragma unroll
        for (int rep = 0; rep < 2; rep++) {
            int idx = t + rep * 256;
            int nn  = idx >> 2;
            int kk4 = (idx & 3) * 4;
            float4 wk = *(const float4*)(Wk + (size_t)(n0 + nn) * CIMG + c0 + kk4);
            float4 wv = *(const float4*)(Wv + (size_t)(n0 + nn) * CIMG + c0 + kk4);
            Bks[kk4 + 0][nn] = wk.x; Bks[kk4 + 1][nn] = wk.y;
            Bks[kk4 + 2][nn] = wk.z; Bks[kk4 + 3][nn] = wk.w;
            Bvs[kk4 + 0][nn] = wv.x; Bvs[kk4 + 1][nn] = wv.y;
            Bvs[kk4 + 2][nn] = wv.z; Bvs[kk4 + 3][nn] = wv.w;
        }
        __syncthreads();
#pragma unroll
        for (int kk = 0; kk < 16; kk++) {
            float4 a4  = *(float4*)&As[kk][ty * 4];
            float4 bk0 = *(float4*)&Bks[kk][tx * 4];
            float4 bk1 = *(float4*)&Bks[kk][tx * 4 + 64];
            float4 bv0 = *(float4*)&Bvs[kk][tx * 4];
            float4 bv1 = *(float4*)&Bvs[kk][tx * 4 + 64];
            float a[4]  = {a4.x, a4.y, a4.z, a4.w};
            float bk[8] = {bk0.x, bk0.y, bk0.z, bk0.w, bk1.x, bk1.y, bk1.z, bk1.w};
            float bv[8] = {bv0.x, bv0.y, bv0.z, bv0.w, bv1.x, bv1.y, bv1.z, bv1.w};
#pragma unroll
            for (int i = 0; i < 4; i++)
#pragma unroll
                for (int j = 0; j < 8; j++) {
                    ak[i][j] += a[i] * bk[j];
                    av[i][j] += a[i] * bv[j];
                }
        }
        __syncthreads();
    }
#pragma unroll
    for (int i = 0; i < 4; i++) {
        int m = m0 + ty * 4 + i;
#pragma unroll
        for (int q = 0; q < 2; q++) {
            int hh = (n0 >> 6) + q;
            __half* dst = g_kv + (size_t)(hh * NPIX + m) * 128 + tx * 4;
            union { uint2 u; __half2 h2[2]; } pk, pv;
            pk.h2[0] = __floats2half2_rn(ak[i][q*4+0], ak[i][q*4+1]);
            pk.h2[1] = __floats2half2_rn(ak[i][q*4+2], ak[i][q*4+3]);
            pv.h2[0] = __floats2half2_rn(av[i][q*4+0], av[i][q*4+1]);
            pv.h2[1] = __floats2half2_rn(av[i][q*4+2], av[i][q*4+3]);
            *(uint2*)dst        = pk.u;
            *(uint2*)(dst + 64) = pv.u;
        }
    }
}

// ---------------------------------------------------------------------------
// Kernel B (fused): q-proj + offsets + deformable attention + out-proj +
//   residual, per gaussian. Block = 1 gaussian (256 thr), warp = 1 head.
//   Lanes 0-15 hold k channels (4 each), 16-31 hold v channels.
// ---------------------------------------------------------------------------
__global__ __launch_bounds__(256) void fused_attn(
    const float* __restrict__ means, const float* __restrict__ scales,
    const float* __restrict__ rots, const float* __restrict__ transforms,
    const float* __restrict__ proj, const float* __restrict__ W_off,
    const float* __restrict__ b_off, const float* __restrict__ feat,
    const float* __restrict__ Wq, const float* __restrict__ Wout,
    const float* __restrict__ b_out, float* __restrict__ out)
{
    const int g    = blockIdx.x;
    const int tid  = threadIdx.x;
    const int h    = tid >> 5;
    const int lane = tid & 31;
    __shared__ float sh_feat[3][GFDIM];
    __shared__ float sh_qm[NH][HDIM];
    __shared__ float sh_learn[NH][18];
    __shared__ float sh_o[NH][3][HDIM];
    __shared__ float sh_part[NH][96];

    if (tid < 96) sh_feat[tid >> 5][tid & 31] = feat[(size_t)g * 96 + tid];
    __syncthreads();

    const int c4 = (lane & 15) * 4;

    // ---- q projection: q[t, h*64+c4..c4+3] ----
    float4 q0 = make_float4(0,0,0,0), q1 = q0, q2 = q0;
    {
        const float* wq = Wq + h * HDIM + c4;
#pragma unroll 8
        for (int k = 0; k < GFDIM; k++) {
            float4 w = *(const float4*)(wq + (size_t)k * AD);
            float f0 = sh_feat[0][k], f1 = sh_feat[1][k], f2 = sh_feat[2][k];
            q0.x += f0*w.x; q0.y += f0*w.y; q0.z += f0*w.z; q0.w += f0*w.w;
            q1.x += f1*w.x; q1.y += f1*w.y; q1.z += f1*w.z; q1.w += f1*w.w;
            q2.x += f2*w.x; q2.y += f2*w.y; q2.z += f2*w.z; q2.w += f2*w.w;
        }
    }

    if (lane < 16) {
        const float inv3 = 1.f / 3.f;
        sh_qm[h][c4 + 0] = (q0.x + q1.x + q2.x) * inv3;
        sh_qm[h][c4 + 1] = (q0.y + q1.y + q2.y) * inv3;
        sh_qm[h][c4 + 2] = (q0.z + q1.z + q2.z) * inv3;
        sh_qm[h][c4 + 3] = (q0.w + q1.w + q2.w) * inv3;
    }
    __syncwarp();

    float mx = means[g*3+0], my = means[g*3+1], mz = means[g*3+2];
    const float* T = transforms + (size_t)g * 16;
    float mwx = T[0]*mx + T[1]*my + T[2] *mz + T[3];
    float mwy = T[4]*mx + T[5]*my + T[6] *mz + T[7];
    float mwz = T[8]*mx + T[9]*my + T[10]*mz + T[11];

    // ---- OffsetNet: lanes 0..17 each produce one of 18 outputs ----
    if (lane < 18) {
        float z = b_off[lane] + mwx*W_off[0*18+lane] + mwy*W_off[1*18+lane]
                + mwz*W_off[2*18+lane];
#pragma unroll 8
        for (int c = 0; c < HDIM; c++) z += sh_qm[h][c] * W_off[(3 + c) * 18 + lane];
        z = fminf(fmaxf(z, -SIGC), SIGC);
        sh_learn[h][lane] = 1.f / (1.f + __expf(-z)) - 0.5f;
    }
    __syncwarp();

    // ---- rotation from normalized quaternion ----
    float qw = rots[g*4+0], qx = rots[g*4+1], qy = rots[g*4+2], qz = rots[g*4+3];
    float qn = rsqrtf(qw*qw + qx*qx + qy*qy + qz*qz);
    qw *= qn; qx *= qn; qy *= qn; qz *= qn;
    float r00 = 1.f-2.f*(qy*qy+qz*qz), r01 = 2.f*(qx*qy-qw*qz), r02 = 2.f*(qx*qz+qw*qy);
    float r10 = 2.f*(qx*qy+qw*qz), r11 = 1.f-2.f*(qx*qx+qz*qz), r12 = 2.f*(qy*qz-qw*qx);
    float r20 = 2.f*(qx*qz-qw*qy), r21 = 2.f*(qy*qz+qw*qx), r22 = 1.f-2.f*(qx*qx+qy*qy);

    float sx = scales[g*3+0], sy = scales[g*3+1], sz = scales[g*3+2];

    // ---- lane kp (<12) computes sample point kp; broadcast via shfl ----
    float fx0 = 0.f, fy0 = 0.f, wx1 = 0.f, wy1 = 0.f;
    {
        int k = lane < 12 ? lane : 11;
        float s0, s1, s2;
        if (k < 6) { s0 = c_fix[k*3+0]; s1 = c_fix[k*3+1]; s2 = c_fix[k*3+2]; }
        else { int l = (k - 6) * 3;
               s0 = sh_learn[h][l]; s1 = sh_learn[h][l+1]; s2 = sh_learn[h][l+2]; }
        float v0 = s0 * sx, v1 = s1 * sy, v2 = s2 * sz;
        float px = r00*v0 + r10*v1 + r20*v2 + mwx;   // R^T v + mean_w
        float py = r01*v0 + r11*v1 + r21*v2 + mwy;
        float pz = r02*v0 + r12*v1 + r22*v2 + mwz;
        float p0 = proj[0]*px + proj[1]*py + proj[2] *pz + proj[3];
        float p1 = proj[4]*px + proj[5]*py + proj[6] *pz + proj[7];
        float p2 = proj[8]*px + proj[9]*py + proj[10]*pz + proj[11];
        float zz = fmaxf(p2, 1e-5f);
        float u = p0 / zz, v = p1 / zz;
        const float lim = 0.9999f * (float)IMG;
        float xf = fminf(fmaxf(u, 0.f), lim) - 0.5f;
        float yf = fminf(fmaxf(v, 0.f), lim) - 0.5f;
        fx0 = floorf(xf); wx1 = xf - fx0;
        fy0 = floorf(yf); wy1 = yf - fy0;
    }

    const __half* kvh = g_kv + (size_t)h * NPIX * 128
                      + (((lane < 16) ? 0 : 64) + c4);

    float s0v = 0.f, s1v = 0.f, s2v = 0.f;
    float4 o0 = make_float4(0,0,0,0), o1 = o0, o2 = o0;

#pragma unroll
    for (int kp = 0; kp < KPTS; kp++) {
        float bx0  = __shfl_sync(0xffffffffu, fx0, kp);
        float by0  = __shfl_sync(0xffffffffu, fy0, kp);
        float bwx1 = __shfl_sync(0xffffffffu, wx1, kp);
        float bwy1 = __shfl_sync(0xffffffffu, wy1, kp);
        int x0 = (int)bx0, y0 = (int)by0;
        float bwx0 = 1.f - bwx1, bwy0 = 1.f - bwy1;
        bool vx0 = (unsigned)x0       < IMG;
        bool vx1 = (unsigned)(x0 + 1) < IMG;
        bool vy0 = (unsigned)y0       < IMG;
        bool vy1 = (unsigned)(y0 + 1) < IMG;
        long ro0 = (long)y0 * (IMG * 128);
        long cx0 = (long)x0 * 128;
        // issue all 4 taps up front (zero-init + predicated) for MLP
        uint2 t00 = make_uint2(0,0), t01 = t00, t10 = t00, t11 = t00;
        if (vy0 && vx0) t00 = *(const uint2*)(kvh + ro0 + cx0);
        if (vy0 && vx1) t01 = *(const uint2*)(kvh + ro0 + cx0 + 128);
        if (vy1 && vx0) t10 = *(const uint2*)(kvh + ro0 + IMG*128 + cx0);
        if (vy1 && vx1) t11 = *(const uint2*)(kvh + ro0 + IMG*128 + cx0 + 128);

        float w00 = bwx0*bwy0, w01 = bwx1*bwy0, w10 = bwx0*bwy1, w11 = bwx1*bwy1;
        float4 acc;
        {
            union { uint2 u; __half2 h2[2]; } c;
            float2 a, b;
            c.u = t00; a = __half22float2(c.h2[0]); b = __half22float2(c.h2[1]);
            acc.x = w00*a.x; acc.y = w00*a.y; acc.z = w00*b.x; acc.w = w00*b.y;
            c.u = t01; a = __half22float2(c.h2[0]); b = __half22float2(c.h2[1]);
            acc.x += w01*a.x; acc.y += w01*a.y; acc.z += w01*b.x; acc.w += w01*b.y;
            c.u = t10; a = __half22float2(c.h2[0]); b = __half22float2(c.h2[1]);
            acc.x += w10*a.x; acc.y += w10*a.y; acc.z += w10*b.x; acc.w += w10*b.y;
            c.u = t11; a = __half22float2(c.h2[0]); b = __half22float2(c.h2[1]);
            acc.x += w11*a.x; acc.y += w11*a.y; acc.z += w11*b.x; acc.w += w11*b.y;
        }

        // scores: reduce q·k within 16-lane groups; k-group result broadcast
        float d0 = q0.x*acc.x + q0.y*acc.y + q0.z*acc.z + q0.w*acc.w;
        float d1 = q1.x*acc.x + q1.y*acc.y + q1.z*acc.z + q1.w*acc.w;
        float d2 = q2.x*acc.x + q2.y*acc.y + q2.z*acc.z + q2.w*acc.w;
#pragma unroll
        for (int off = 8; off > 0; off >>= 1) {
            d0 += __shfl_xor_sync(0xffffffffu, d0, off);
            d1 += __shfl_xor_sync(0xffffffffu, d1, off);
            d2 += __shfl_xor_sync(0xffffffffu, d2, off);
        }
        d0 = __shfl_sync(0xffffffffu, d0, lane & 15) * 0.125f;
        d1 = __shfl_sync(0xffffffffu, d1, lane & 15) * 0.125f;
        d2 = __shfl_sync(0xffffffffu, d2, lane & 15) * 0.125f;
        float e0 = __expf(d0), e1 = __expf(d1), e2 = __expf(d2);
        s0v += e0; s1v += e1; s2v += e2;
        o0.x += e0*acc.x; o0.y += e0*acc.y; o0.z += e0*acc.z; o0.w += e0*acc.w;
        o1.x += e1*acc.x; o1.y += e1*acc.y; o1.z += e1*acc.z; o1.w += e1*acc.w;
        o2.x += e2*acc.x; o2.y += e2*acc.y; o2.z += e2*acc.z; o2.w += e2*acc.w;
    }

    // ---- normalize + stage per-head attention output in smem ----
    if (lane >= 16) {
        float i0 = 1.f / s0v, i1 = 1.f / s1v, i2 = 1.f / s2v;
        *(float4*)&sh_o[h][0][c4] = make_float4(o0.x*i0, o0.y*i0, o0.z*i0, o0.w*i0);
        *(float4*)&sh_o[h][1][c4] = make_float4(o1.x*i1, o1.y*i1, o1.z*i1, o1.w*i1);
        *(float4*)&sh_o[h][2][c4] = make_float4(o2.x*i2, o2.y*i2, o2.z*i2, o2.w*i2);
    }
    __syncwarp();

    // ---- per-head output projection: partial[t][c] over this head's 64 ch ----
    float a0 = 0.f, a1 = 0.f, a2 = 0.f;
    {
        const float* wo = Wout + (size_t)(h * HDIM) * GFDIM + lane;
#pragma unroll 8
        for (int j = 0; j < HDIM; j++) {
            float w = wo[(size_t)j * GFDIM];
            a0 += sh_o[h][0][j] * w;
            a1 += sh_o[h][1][j] * w;
            a2 += sh_o[h][2][j] * w;
        }
    }
    sh_part[h][lane]      = a0;
    sh_part[h][32 + lane] = a1;
    sh_part[h][64 + lane] = a2;
    __syncthreads();

    // ---- deterministic cross-head reduce + bias + residual ----
    if (tid < 96) {
        float s = 0.f;
#pragma unroll
        for (int hh = 0; hh < NH; hh++) s += sh_part[hh][tid];
        int c = tid & 31;
        out[(size_t)g * 96 + tid] = s + b_out[c] + sh_feat[tid >> 5][c];
    }
}

// ---------------------------------------------------------------------------
extern "C" void kernel_launch(void* const* d_in, const int* in_sizes, int n_in,
                              void* d_out, int out_size)
{
    const float* means      = (const float*)d_in[0];
    const float* scales     = (const float*)d_in[1];
    const float* rotations  = (const float*)d_in[2];
    const float* features   = (const float*)d_in[3];
    const float* transforms = (const float*)d_in[4];
    const float* projection = (const float*)d_in[5];
    const float* image_feat = (const float*)d_in[6];
    const float* Wq         = (const float*)d_in[7];
    const float* Wk         = (const float*)d_in[8];
    const float* Wv         = (const float*)d_in[9];
    const float* W_off      = (const float*)d_in[10];
    const float* b_off      = (const float*)d_in[11];
    const float* Wout       = (const float*)d_in[12];
    const float* b_out      = (const float*)d_in[13];
    float* out = (float*)d_out;

    kv_gemm<<<dim3(NPIX / 64, AD / 128), 256>>>(image_feat, Wk, Wv);
    fused_attn<<<G_N, 256>>>(means, scales, rotations, transforms,
                             projection, W_off, b_off, features,
                             Wq, Wout, b_out, out);
}

// round 4
// speedup vs baseline: 1.1234x; 1.1234x over previous
#include <cuda_runtime.h>
#include <cuda_fp16.h>

#define G_N   8192
#define NH    8
#define HDIM  64
#define AD    512
#define GFDIM 32
#define CIMG  256
#define IMG   64
#define NPIX  (IMG*IMG)
#define KPTS  12
#define SIGC  9.21f

typedef unsigned long long u64t;

// ---- packed f32x2 helpers (Blackwell FFMA2 path; ptxas never auto-fuses) ----
__device__ __forceinline__ u64t ffma2(u64t a, u64t b, u64t c) {
    u64t d; asm("fma.rn.f32x2 %0, %1, %2, %3;" : "=l"(d) : "l"(a), "l"(b), "l"(c));
    return d;
}
__device__ __forceinline__ u64t fmul2(u64t a, u64t b) {
    u64t d; asm("mul.rn.f32x2 %0, %1, %2;" : "=l"(d) : "l"(a), "l"(b)); return d;
}
__device__ __forceinline__ u64t fadd2(u64t a, u64t b) {
    u64t d; asm("add.rn.f32x2 %0, %1, %2;" : "=l"(d) : "l"(a), "l"(b)); return d;
}
__device__ __forceinline__ u64t splat2(float x) {
    u64t d; asm("mov.b64 %0, {%1, %1};" : "=l"(d) : "f"(x)); return d;
}
__device__ __forceinline__ u64t pk2(float x, float y) {
    u64t d; asm("mov.b64 %0, {%1, %2};" : "=l"(d) : "f"(x), "f"(y)); return d;
}
__device__ __forceinline__ float2 unpk(u64t a) {
    float2 r; asm("mov.b64 {%0, %1}, %2;" : "=f"(r.x), "=f"(r.y) : "l"(a)); return r;
}

// Scratch: kv maps fp16, interleaved [h][pix][k0..63 | v0..63]  (8 MB, L2-resident)
__device__ __half g_kv[NH * NPIX * 128];

__constant__ float c_fix[18] = {0,0,0, 1,0,0, 0,1,0, 0,0,1, -1,0,0, 0,-1,0};

// ---------------------------------------------------------------------------
// Kernel A: kmap/vmap = Wk/Wv @ image_features -> fp16 interleaved g_kv.
//   M=4096 pixels, N=512, K=256. Tile 64x128, TK=16. FFMA2 inner loop.
// ---------------------------------------------------------------------------
__global__ __launch_bounds__(256) void kv_gemm(
    const float* __restrict__ img, const float* __restrict__ Wk,
    const float* __restrict__ Wv)
{
    const int m0 = blockIdx.x * 64;
    const int n0 = blockIdx.y * 128;
    __shared__ float As[16][64];
    __shared__ float Bks[16][128];
    __shared__ float Bvs[16][128];
    const int t  = threadIdx.x;
    const int tx = t & 15, ty = t >> 4;

    u64t ak2[4][4], av2[4][4];   // [row i][channel pair j] (8 cols = 4 pairs)
#pragma unroll
    for (int i = 0; i < 4; i++)
#pragma unroll
        for (int j = 0; j < 4; j++) { ak2[i][j] = 0ull; av2[i][j] = 0ull; }

    for (int c0 = 0; c0 < CIMG; c0 += 16) {
        *(float4*)&As[ty][tx * 4] =
            *(const float4*)(img + (size_t)(c0 + ty) * NPIX + m0 + tx * 4);
#pragma unroll
        for (int rep = 0; rep < 2; rep++) {
            int idx = t + rep * 256;
            int nn  = idx >> 2;
            int kk4 = (idx & 3) * 4;
            float4 wk = *(const float4*)(Wk + (size_t)(n0 + nn) * CIMG + c0 + kk4);
            float4 wv = *(const float4*)(Wv + (size_t)(n0 + nn) * CIMG + c0 + kk4);
            Bks[kk4 + 0][nn] = wk.x; Bks[kk4 + 1][nn] = wk.y;
            Bks[kk4 + 2][nn] = wk.z; Bks[kk4 + 3][nn] = wk.w;
            Bvs[kk4 + 0][nn] = wv.x; Bvs[kk4 + 1][nn] = wv.y;
            Bvs[kk4 + 2][nn] = wv.z; Bvs[kk4 + 3][nn] = wv.w;
        }
        __syncthreads();
#pragma unroll
        for (int kk = 0; kk < 16; kk++) {
            float4 a4 = *(float4*)&As[kk][ty * 4];
            ulonglong2 bkl = *(ulonglong2*)&Bks[kk][tx * 4];
            ulonglong2 bkh = *(ulonglong2*)&Bks[kk][tx * 4 + 64];
            ulonglong2 bvl = *(ulonglong2*)&Bvs[kk][tx * 4];
            ulonglong2 bvh = *(ulonglong2*)&Bvs[kk][tx * 4 + 64];
            u64t bk[4] = {bkl.x, bkl.y, bkh.x, bkh.y};
            u64t bv[4] = {bvl.x, bvl.y, bvh.x, bvh.y};
            float a[4] = {a4.x, a4.y, a4.z, a4.w};
#pragma unroll
            for (int i = 0; i < 4; i++) {
                u64t as = splat2(a[i]);
#pragma unroll
                for (int j = 0; j < 4; j++) {
                    ak2[i][j] = ffma2(as, bk[j], ak2[i][j]);
                    av2[i][j] = ffma2(as, bv[j], av2[i][j]);
                }
            }
        }
        __syncthreads();
    }
#pragma unroll
    for (int i = 0; i < 4; i++) {
        int m = m0 + ty * 4 + i;
#pragma unroll
        for (int q = 0; q < 2; q++) {
            int hh = (n0 >> 6) + q;
            __half* dst = g_kv + (size_t)(hh * NPIX + m) * 128 + tx * 4;
            float2 k0 = unpk(ak2[i][q*2+0]), k1 = unpk(ak2[i][q*2+1]);
            float2 v0 = unpk(av2[i][q*2+0]), v1 = unpk(av2[i][q*2+1]);
            union { uint2 u; __half2 h2[2]; } pk, pv;
            pk.h2[0] = __floats2half2_rn(k0.x, k0.y);
            pk.h2[1] = __floats2half2_rn(k1.x, k1.y);
            pv.h2[0] = __floats2half2_rn(v0.x, v0.y);
            pv.h2[1] = __floats2half2_rn(v1.x, v1.y);
            *(uint2*)dst        = pk.u;
            *(uint2*)(dst + 64) = pv.u;
        }
    }
}

// ---------------------------------------------------------------------------
// Kernel B (fused): q-proj + offsets + deformable attention + out-proj +
//   residual.  Block = 1 gaussian (256 thr), warp = 1 head.
//   q-proj: lane owns channel pair 2*lane (no k/v duplication), FFMA2.
//   Gather: lanes 0-15 k channels (4 each), 16-31 v channels.
// ---------------------------------------------------------------------------
__global__ __launch_bounds__(256) void fused_attn(
    const float* __restrict__ means, const float* __restrict__ scales,
    const float* __restrict__ rots, const float* __restrict__ transforms,
    const float* __restrict__ proj, const float* __restrict__ W_off,
    const float* __restrict__ b_off, const float* __restrict__ feat,
    const float* __restrict__ Wq, const float* __restrict__ Wout,
    const float* __restrict__ b_out, float* __restrict__ out)
{
    const int g    = blockIdx.x;
    const int tid  = threadIdx.x;
    const int h    = tid >> 5;
    const int lane = tid & 31;
    __shared__ float2 sh_f2[3][GFDIM];          // (f,f) splat table
    __shared__ float  sh_qm[NH][HDIM];
    __shared__ float  sh_learn[NH][18];
    __shared__ float  sh_o[NH][3][HDIM];
    __shared__ float  sh_part[NH][96];

    if (tid < 96) {
        float f = feat[(size_t)g * 96 + tid];
        sh_f2[tid >> 5][tid & 31] = make_float2(f, f);
    }
    __syncthreads();

    // ---- q projection: lane owns channels (2*lane, 2*lane+1) of this head ----
    u64t qp0 = 0ull, qp1 = 0ull, qp2 = 0ull;
    {
        const float* wq = Wq + h * HDIM + lane * 2;
#pragma unroll 8
        for (int k = 0; k < GFDIM; k++) {
            u64t w  = *(const u64t*)(wq + (size_t)k * AD);
            qp0 = ffma2(*(const u64t*)&sh_f2[0][k], w, qp0);
            qp1 = ffma2(*(const u64t*)&sh_f2[1][k], w, qp1);
            qp2 = ffma2(*(const u64t*)&sh_f2[2][k], w, qp2);
        }
    }
    {   // token-mean of q for OffsetNet (all 32 lanes cover all 64 channels)
        u64t qm = fmul2(fadd2(fadd2(qp0, qp1), qp2), splat2(1.f / 3.f));
        *(float2*)&sh_qm[h][lane * 2] = unpk(qm);
    }
    __syncwarp();

    // redistribute packed q to gather layout: lane needs channels c4..c4+3
    const int src = (lane & 15) * 2;
    u64t q0a = __shfl_sync(0xffffffffu, qp0, src);
    u64t q0b = __shfl_sync(0xffffffffu, qp0, src + 1);
    u64t q1a = __shfl_sync(0xffffffffu, qp1, src);
    u64t q1b = __shfl_sync(0xffffffffu, qp1, src + 1);
    u64t q2a = __shfl_sync(0xffffffffu, qp2, src);
    u64t q2b = __shfl_sync(0xffffffffu, qp2, src + 1);

    float mx = means[g*3+0], my = means[g*3+1], mz = means[g*3+2];
    const float* T = transforms + (size_t)g * 16;
    float mwx = T[0]*mx + T[1]*my + T[2] *mz + T[3];
    float mwy = T[4]*mx + T[5]*my + T[6] *mz + T[7];
    float mwz = T[8]*mx + T[9]*my + T[10]*mz + T[11];

    // ---- OffsetNet: lanes 0..17 each produce one of 18 outputs ----
    if (lane < 18) {
        float z = b_off[lane] + mwx*W_off[0*18+lane] + mwy*W_off[1*18+lane]
                + mwz*W_off[2*18+lane];
#pragma unroll 8
        for (int c = 0; c < HDIM; c++) z += sh_qm[h][c] * W_off[(3 + c) * 18 + lane];
        z = fminf(fmaxf(z, -SIGC), SIGC);
        sh_learn[h][lane] = 1.f / (1.f + __expf(-z)) - 0.5f;
    }
    __syncwarp();

    // ---- rotation from normalized quaternion ----
    float qw = rots[g*4+0], qx = rots[g*4+1], qy = rots[g*4+2], qz = rots[g*4+3];
    float qn = rsqrtf(qw*qw + qx*qx + qy*qy + qz*qz);
    qw *= qn; qx *= qn; qy *= qn; qz *= qn;
    float r00 = 1.f-2.f*(qy*qy+qz*qz), r01 = 2.f*(qx*qy-qw*qz), r02 = 2.f*(qx*qz+qw*qy);
    float r10 = 2.f*(qx*qy+qw*qz), r11 = 1.f-2.f*(qx*qx+qz*qz), r12 = 2.f*(qy*qz-qw*qx);
    float r20 = 2.f*(qx*qz-qw*qy), r21 = 2.f*(qy*qz+qw*qx), r22 = 1.f-2.f*(qx*qx+qy*qy);

    float sx = scales[g*3+0], sy = scales[g*3+1], sz = scales[g*3+2];

    // ---- lane kp (<12): sample point kp -> base index + validity + weights ----
    int   base = 0, fl = 0;
    float wx1 = 0.f, wy1 = 0.f;
    {
        int k = lane < 12 ? lane : 11;
        float s0, s1, s2;
        if (k < 6) { s0 = c_fix[k*3+0]; s1 = c_fix[k*3+1]; s2 = c_fix[k*3+2]; }
        else { int l = (k - 6) * 3;
               s0 = sh_learn[h][l]; s1 = sh_learn[h][l+1]; s2 = sh_learn[h][l+2]; }
        float v0 = s0 * sx, v1 = s1 * sy, v2 = s2 * sz;
        float px = r00*v0 + r10*v1 + r20*v2 + mwx;   // R^T v + mean_w
        float py = r01*v0 + r11*v1 + r21*v2 + mwy;
        float pz = r02*v0 + r12*v1 + r22*v2 + mwz;
        float p0 = proj[0]*px + proj[1]*py + proj[2] *pz + proj[3];
        float p1 = proj[4]*px + proj[5]*py + proj[6] *pz + proj[7];
        float p2 = proj[8]*px + proj[9]*py + proj[10]*pz + proj[11];
        float zz = fmaxf(p2, 1e-5f);
        float u = p0 / zz, v = p1 / zz;
        const float lim = 0.9999f * (float)IMG;
        float xf = fminf(fmaxf(u, 0.f), lim) - 0.5f;
        float yf = fminf(fmaxf(v, 0.f), lim) - 0.5f;
        float fx0 = floorf(xf); wx1 = xf - fx0;
        float fy0 = floorf(yf); wy1 = yf - fy0;
        int x0 = (int)fx0, y0 = (int)fy0;
        base = (y0 * IMG + x0) * 128;
        int vx0 = (unsigned)x0       < IMG;
        int vx1 = (unsigned)(x0 + 1) < IMG;
        int vy0 = (unsigned)y0       < IMG;
        int vy1 = (unsigned)(y0 + 1) < IMG;
        fl = (vy0 & vx0) | ((vy0 & vx1) << 1) | ((vy1 & vx0) << 2) | ((vy1 & vx1) << 3);
    }

    const __half* kvh = g_kv + (size_t)h * NPIX * 128
                      + (((lane < 16) ? 0 : 64) + (lane & 15) * 4);

    float s0v = 0.f, s1v = 0.f, s2v = 0.f;
    u64t o0a = 0ull, o0b = 0ull, o1a = 0ull, o1b = 0ull, o2a = 0ull, o2b = 0ull;

#pragma unroll
    for (int kp = 0; kp < KPTS; kp++) {
        int   bb   = __shfl_sync(0xffffffffu, base, kp);
        int   bf   = __shfl_sync(0xffffffffu, fl,   kp);
        float bwx1 = __shfl_sync(0xffffffffu, wx1,  kp);
        float bwy1 = __shfl_sync(0xffffffffu, wy1,  kp);
        float bwx0 = 1.f - bwx1, bwy0 = 1.f - bwy1;
        const __half* p = kvh + bb;
        uint2 t00 = make_uint2(0,0), t01 = t00, t10 = t00, t11 = t00;
        if (bf & 1) t00 = *(const uint2*)(p);
        if (bf & 2) t01 = *(const uint2*)(p + 128);
        if (bf & 4) t10 = *(const uint2*)(p + IMG*128);
        if (bf & 8) t11 = *(const uint2*)(p + IMG*128 + 128);

        float w00 = bwx0*bwy0, w01 = bwx1*bwy0, w10 = bwx0*bwy1, w11 = bwx1*bwy1;
        float4 acc;
        {
            union { uint2 u; __half2 h2[2]; } c;
            float2 a, b;
            c.u = t00; a = __half22float2(c.h2[0]); b = __half22float2(c.h2[1]);
            acc.x = w00*a.x; acc.y = w00*a.y; acc.z = w00*b.x; acc.w = w00*b.y;
            c.u = t01; a = __half22float2(c.h2[0]); b = __half22float2(c.h2[1]);
            acc.x += w01*a.x; acc.y += w01*a.y; acc.z += w01*b.x; acc.w += w01*b.y;
            c.u = t10; a = __half22float2(c.h2[0]); b = __half22float2(c.h2[1]);
            acc.x += w10*a.x; acc.y += w10*a.y; acc.z += w10*b.x; acc.w += w10*b.y;
            c.u = t11; a = __half22float2(c.h2[0]); b = __half22float2(c.h2[1]);
            acc.x += w11*a.x; acc.y += w11*a.y; acc.z += w11*b.x; acc.w += w11*b.y;
        }
        u64t acc_a = pk2(acc.x, acc.y), acc_b = pk2(acc.z, acc.w);

        // scores (k lanes valid): packed partial dots then horizontal add
        float2 p0v = unpk(ffma2(q0a, acc_a, fmul2(q0b, acc_b)));
        float2 p1v = unpk(ffma2(q1a, acc_a, fmul2(q1b, acc_b)));
        float2 p2v = unpk(ffma2(q2a, acc_a, fmul2(q2b, acc_b)));
        float d0 = p0v.x + p0v.y, d1 = p1v.x + p1v.y, d2 = p2v.x + p2v.y;
#pragma unroll
        for (int off = 8; off > 0; off >>= 1) {
            d0 += __shfl_xor_sync(0xffffffffu, d0, off);
            d1 += __shfl_xor_sync(0xffffffffu, d1, off);
            d2 += __shfl_xor_sync(0xffffffffu, d2, off);
        }
        d0 = __shfl_sync(0xffffffffu, d0, lane & 15) * 0.125f;
        d1 = __shfl_sync(0xffffffffu, d1, lane & 15) * 0.125f;
        d2 = __shfl_sync(0xffffffffu, d2, lane & 15) * 0.125f;
        float e0 = __expf(d0), e1 = __expf(d1), e2 = __expf(d2);
        s0v += e0; s1v += e1; s2v += e2;
        u64t e0p = splat2(e0), e1p = splat2(e1), e2p = splat2(e2);
        o0a = ffma2(e0p, acc_a, o0a); o0b = ffma2(e0p, acc_b, o0b);
        o1a = ffma2(e1p, acc_a, o1a); o1b = ffma2(e1p, acc_b, o1b);
        o2a = ffma2(e2p, acc_a, o2a); o2b = ffma2(e2p, acc_b, o2b);
    }

    // ---- normalize + stage per-head attention output in smem ----
    if (lane >= 16) {
        const int c4 = (lane & 15) * 4;
        u64t i0 = splat2(1.f / s0v), i1 = splat2(1.f / s1v), i2 = splat2(1.f / s2v);
        *(float2*)&sh_o[h][0][c4]     = unpk(fmul2(o0a, i0));
        *(float2*)&sh_o[h][0][c4 + 2] = unpk(fmul2(o0b, i0));
        *(float2*)&sh_o[h][1][c4]     = unpk(fmul2(o1a, i1));
        *(float2*)&sh_o[h][1][c4 + 2] = unpk(fmul2(o1b, i1));
        *(float2*)&sh_o[h][2][c4]     = unpk(fmul2(o2a, i2));
        *(float2*)&sh_o[h][2][c4 + 2] = unpk(fmul2(o2b, i2));
    }
    __syncwarp();

    // ---- per-head output projection, packed over j pairs ----
    u64t ap0 = 0ull, ap1 = 0ull, ap2 = 0ull;
    {
        const float* wo = Wout + (size_t)(h * HDIM) * GFDIM + lane;
#pragma unroll 8
        for (int j = 0; j < HDIM; j += 2) {
            u64t wpk = pk2(wo[(size_t)j * GFDIM], wo[(size_t)(j + 1) * GFDIM]);
            ap0 = ffma2(*(const u64t*)&sh_o[h][0][j], wpk, ap0);
            ap1 = ffma2(*(const u64t*)&sh_o[h][1][j], wpk, ap1);
            ap2 = ffma2(*(const u64t*)&sh_o[h][2][j], wpk, ap2);
        }
    }
    float2 r0 = unpk(ap0), r1 = unpk(ap1), r2 = unpk(ap2);
    sh_part[h][lane]      = r0.x + r0.y;
    sh_part[h][32 + lane] = r1.x + r1.y;
    sh_part[h][64 + lane] = r2.x + r2.y;
    __syncthreads();

    // ---- deterministic cross-head reduce + bias + residual ----
    if (tid < 96) {
        float s = 0.f;
#pragma unroll
        for (int hh = 0; hh < NH; hh++) s += sh_part[hh][tid];
        int c = tid & 31;
        out[(size_t)g * 96 + tid] = s + b_out[c] + sh_f2[tid >> 5][c].x;
    }
}

// ---------------------------------------------------------------------------
extern "C" void kernel_launch(void* const* d_in, const int* in_sizes, int n_in,
                              void* d_out, int out_size)
{
    const float* means      = (const float*)d_in[0];
    const float* scales     = (const float*)d_in[1];
    const float* rotations  = (const float*)d_in[2];
    const float* features   = (const float*)d_in[3];
    const float* transforms = (const float*)d_in[4];
    const float* projection = (const float*)d_in[5];
    const float* image_feat = (const float*)d_in[6];
    const float* Wq         = (const float*)d_in[7];
    const float* Wk         = (const float*)d_in[8];
    const float* Wv         = (const float*)d_in[9];
    const float* W_off      = (const float*)d_in[10];
    const float* b_off      = (const float*)d_in[11];
    const float* Wout       = (const float*)d_in[12];
    const float* b_out      = (const float*)d_in[13];
    float* out = (float*)d_out;

    kv_gemm<<<dim3(NPIX / 64, AD / 128), 256>>>(image_feat, Wk, Wv);
    fused_attn<<<G_N, 256>>>(means, scales, rotations, transforms,
                             projection, W_off, b_off, features,
                             Wq, Wout, b_out, out);
}

// round 5
// speedup vs baseline: 1.2604x; 1.1219x over previous
#include <cuda_runtime.h>
#include <cuda_fp16.h>

#define G_N   8192
#define NH    8
#define HDIM  64
#define AD    512
#define GFDIM 32
#define CIMG  256
#define IMG   64
#define NPIX  (IMG*IMG)
#define KPTS  12
#define SIGC  9.21f
#define NGH   (G_N * NH)

typedef unsigned long long u64t;

// ---- packed f32x2 helpers ----
__device__ __forceinline__ u64t ffma2(u64t a, u64t b, u64t c) {
    u64t d; asm("fma.rn.f32x2 %0, %1, %2, %3;" : "=l"(d) : "l"(a), "l"(b), "l"(c));
    return d;
}
__device__ __forceinline__ u64t fmul2(u64t a, u64t b) {
    u64t d; asm("mul.rn.f32x2 %0, %1, %2;" : "=l"(d) : "l"(a), "l"(b)); return d;
}
__device__ __forceinline__ u64t fadd2(u64t a, u64t b) {
    u64t d; asm("add.rn.f32x2 %0, %1, %2;" : "=l"(d) : "l"(a), "l"(b)); return d;
}
__device__ __forceinline__ u64t splat2(float x) {
    u64t d; asm("mov.b64 %0, {%1, %1};" : "=l"(d) : "f"(x)); return d;
}
__device__ __forceinline__ u64t pk2(float x, float y) {
    u64t d; asm("mov.b64 %0, {%1, %2};" : "=l"(d) : "f"(x), "f"(y)); return d;
}
__device__ __forceinline__ float2 unpk(u64t a) {
    float2 r; asm("mov.b64 {%0, %1}, %2;" : "=f"(r.x), "=f"(r.y) : "l"(a)); return r;
}
__device__ __forceinline__ u64t shflx64(u64t v, int m) {
    float2 f = unpk(v);
    f.x = __shfl_xor_sync(0xffffffffu, f.x, m);
    f.y = __shfl_xor_sync(0xffffffffu, f.y, m);
    return pk2(f.x, f.y);
}

// Scratch buffers (static device globals; ~100MB total, L2-resident working set)
__device__ __half g_kv[NH * NPIX * 128];     // [h][pix][lane16: k4|v4 interleaved] 8MB
__device__ float  g_q[G_N * 3 * AD];         // [g*3+t][h*64+c]  50MB
__device__ float  g_learn[NGH * 18];         // sigmoid(..)-0.5   4.7MB
__device__ int4   g_pts[NGH * KPTS];         // {base_bytes, flags, wx1, wy1} 12.6MB
__device__ __half g_attn[G_N * 3 * AD];      // attention out fp16 25MB

__constant__ float c_fix[18] = {0,0,0, 1,0,0, 0,1,0, 0,0,1, -1,0,0, 0,-1,0};

// ---------------------------------------------------------------------------
// K1: kmap/vmap -> fp16 g_kv, layout per pixel (256B): lane l in 0..15 owns
//     bytes l*16..+7 = k[4l..4l+3], +8..+15 = v[4l..4l+3].
// ---------------------------------------------------------------------------
__global__ __launch_bounds__(256) void kv_gemm(
    const float* __restrict__ img, const float* __restrict__ Wk,
    const float* __restrict__ Wv)
{
    const int m0 = blockIdx.x * 64;
    const int n0 = blockIdx.y * 128;
    __shared__ float As[16][64];
    __shared__ float Bks[16][128];
    __shared__ float Bvs[16][128];
    const int t  = threadIdx.x;
    const int tx = t & 15, ty = t >> 4;

    u64t ak2[4][4], av2[4][4];
#pragma unroll
    for (int i = 0; i < 4; i++)
#pragma unroll
        for (int j = 0; j < 4; j++) { ak2[i][j] = 0ull; av2[i][j] = 0ull; }

    for (int c0 = 0; c0 < CIMG; c0 += 16) {
        *(float4*)&As[ty][tx * 4] =
            *(const float4*)(img + (size_t)(c0 + ty) * NPIX + m0 + tx * 4);
#pragma unroll
        for (int rep = 0; rep < 2; rep++) {
            int idx = t + rep * 256;
            int nn  = idx >> 2;
            int kk4 = (idx & 3) * 4;
            float4 wk = *(const float4*)(Wk + (size_t)(n0 + nn) * CIMG + c0 + kk4);
            float4 wv = *(const float4*)(Wv + (size_t)(n0 + nn) * CIMG + c0 + kk4);
            Bks[kk4 + 0][nn] = wk.x; Bks[kk4 + 1][nn] = wk.y;
            Bks[kk4 + 2][nn] = wk.z; Bks[kk4 + 3][nn] = wk.w;
            Bvs[kk4 + 0][nn] = wv.x; Bvs[kk4 + 1][nn] = wv.y;
            Bvs[kk4 + 2][nn] = wv.z; Bvs[kk4 + 3][nn] = wv.w;
        }
        __syncthreads();
#pragma unroll
        for (int kk = 0; kk < 16; kk++) {
            float4 a4 = *(float4*)&As[kk][ty * 4];
            ulonglong2 bkl = *(ulonglong2*)&Bks[kk][tx * 4];
            ulonglong2 bkh = *(ulonglong2*)&Bks[kk][tx * 4 + 64];
            ulonglong2 bvl = *(ulonglong2*)&Bvs[kk][tx * 4];
            ulonglong2 bvh = *(ulonglong2*)&Bvs[kk][tx * 4 + 64];
            u64t bk[4] = {bkl.x, bkl.y, bkh.x, bkh.y};
            u64t bv[4] = {bvl.x, bvl.y, bvh.x, bvh.y};
            float a[4] = {a4.x, a4.y, a4.z, a4.w};
#pragma unroll
            for (int i = 0; i < 4; i++) {
                u64t as = splat2(a[i]);
#pragma unroll
                for (int j = 0; j < 4; j++) {
                    ak2[i][j] = ffma2(as, bk[j], ak2[i][j]);
                    av2[i][j] = ffma2(as, bv[j], av2[i][j]);
                }
            }
        }
        __syncthreads();
    }
#pragma unroll
    for (int i = 0; i < 4; i++) {
        int m = m0 + ty * 4 + i;
#pragma unroll
        for (int q = 0; q < 2; q++) {
            int hh = (n0 >> 6) + q;
            __half* dst = g_kv + ((size_t)(hh * NPIX + m)) * 128 + tx * 8;
            float2 k0 = unpk(ak2[i][q*2+0]), k1 = unpk(ak2[i][q*2+1]);
            float2 v0 = unpk(av2[i][q*2+0]), v1 = unpk(av2[i][q*2+1]);
            union { uint4 u; __half2 h2[4]; } p;
            p.h2[0] = __floats2half2_rn(k0.x, k0.y);
            p.h2[1] = __floats2half2_rn(k1.x, k1.y);
            p.h2[2] = __floats2half2_rn(v0.x, v0.y);
            p.h2[3] = __floats2half2_rn(v1.x, v1.y);
            *(uint4*)dst = p.u;
        }
    }
}

// ---------------------------------------------------------------------------
// K2: q = features @ Wq.  M=24576, K=32, N=512.  (R2-proven tiling)
// ---------------------------------------------------------------------------
__global__ __launch_bounds__(256) void q_gemm(
    const float* __restrict__ feat, const float* __restrict__ Wq)
{
    const int r0 = blockIdx.x * 64;
    const int n0 = blockIdx.y * 256;
    __shared__ float Fs[64][32];
    __shared__ float Ws[32][256];
    const int t = threadIdx.x;
#pragma unroll
    for (int rep = 0; rep < 8; rep++) {
        int idx = t + rep * 256;
        Fs[idx >> 5][idx & 31] = feat[(size_t)(r0 + (idx >> 5)) * GFDIM + (idx & 31)];
    }
#pragma unroll
    for (int rep = 0; rep < 8; rep++) {
        int idx = t + rep * 256;
        int k = idx >> 6, n4 = (idx & 63) << 2;
        *(float4*)&Ws[k][n4] = *(const float4*)(Wq + (size_t)k * AD + n0 + n4);
    }
    __syncthreads();

    const int tc = t & 15, tr = t >> 4;
    float acc[4][16];
#pragma unroll
    for (int i = 0; i < 4; i++)
#pragma unroll
        for (int j = 0; j < 16; j++) acc[i][j] = 0.f;

#pragma unroll
    for (int k = 0; k < 32; k++) {
        float f[4];
#pragma unroll
        for (int i = 0; i < 4; i++) f[i] = Fs[tr * 4 + i][k];
        float w[16];
#pragma unroll
        for (int q = 0; q < 4; q++) {
            float4 w4 = *(float4*)&Ws[k][q * 64 + tc * 4];
            w[q*4+0] = w4.x; w[q*4+1] = w4.y; w[q*4+2] = w4.z; w[q*4+3] = w4.w;
        }
#pragma unroll
        for (int i = 0; i < 4; i++)
#pragma unroll
            for (int j = 0; j < 16; j++) acc[i][j] += f[i] * w[j];
    }
#pragma unroll
    for (int i = 0; i < 4; i++) {
        int r = r0 + tr * 4 + i;
#pragma unroll
        for (int q = 0; q < 4; q++)
            *(float4*)&g_q[(size_t)r * AD + n0 + q * 64 + tc * 4] =
                make_float4(acc[i][q*4+0], acc[i][q*4+1], acc[i][q*4+2], acc[i][q*4+3]);
    }
}

// ---------------------------------------------------------------------------
// K3: sig_gemm — learn[r][o] = sigmoid(clip([mw,qmean] @ W_off + b)) - 0.5
//     rows r = g*8+h (64 per block), K = 67, N = 18.
// ---------------------------------------------------------------------------
__global__ __launch_bounds__(256) void sig_gemm(
    const float* __restrict__ means, const float* __restrict__ transforms,
    const float* __restrict__ W_off, const float* __restrict__ b_off)
{
    const int r0 = blockIdx.x * 64;
    __shared__ float Xs[64][69];      // [row][67 inputs], padded stride 69 (conflict-free)
    __shared__ float Ws[67][20];      // cols 18,19 zero-padded
    __shared__ float bs[20];
    const int t = threadIdx.x;

    for (int idx = t; idx < 64 * 64; idx += 256) {
        int rl = idx >> 6, c = idx & 63;
        int r = r0 + rl, g = r >> 3, h = r & 7;
        const float* q = g_q + (size_t)(g * 3) * AD + h * HDIM + c;
        Xs[rl][3 + c] = (q[0] + q[AD] + q[2 * AD]) * (1.f / 3.f);
    }
    if (t < 64) {
        int r = r0 + t, g = r >> 3;
        float mx = means[g*3], my = means[g*3+1], mz = means[g*3+2];
        const float* T = transforms + (size_t)g * 16;
        Xs[t][0] = T[0]*mx + T[1]*my + T[2] *mz + T[3];
        Xs[t][1] = T[4]*mx + T[5]*my + T[6] *mz + T[7];
        Xs[t][2] = T[8]*mx + T[9]*my + T[10]*mz + T[11];
    }
    for (int idx = t; idx < 67 * 20; idx += 256) {
        int i = idx / 20, o = idx % 20;
        Ws[i][o] = (o < 18) ? W_off[i * 18 + o] : 0.f;
    }
    if (t < 20) bs[t] = (t < 18) ? b_off[t] : 0.f;
    __syncthreads();

    const int rl = t & 63, og = t >> 6;          // og*5 .. og*5+4 (og=3 -> 15..17)
    const int obase = og * 5;
    float acc[5] = {0.f, 0.f, 0.f, 0.f, 0.f};
    for (int i = 0; i < 67; i++) {
        float x = Xs[rl][i];
#pragma unroll
        for (int u = 0; u < 5; u++) acc[u] += x * Ws[i][obase + u];
    }
    const int on = (og == 3) ? 3 : 5;
    for (int u = 0; u < on; u++) {
        float z = acc[u] + bs[obase + u];
        z = fminf(fmaxf(z, -SIGC), SIGC);
        g_learn[(size_t)(r0 + rl) * 18 + obase + u] = 1.f / (1.f + __expf(-z)) - 0.5f;
    }
}

// ---------------------------------------------------------------------------
// K4: pointprep — per (g,h,kp) sample point: base byte offset, validity flags,
//     bilinear weights.  786432 threads.
// ---------------------------------------------------------------------------
__global__ __launch_bounds__(256) void pointprep(
    const float* __restrict__ means, const float* __restrict__ scales,
    const float* __restrict__ rots, const float* __restrict__ transforms,
    const float* __restrict__ proj)
{
    int id = blockIdx.x * 256 + threadIdx.x;      // exactly NGH*KPTS
    int kp = id % KPTS;
    int r  = id / KPTS;
    int g  = r >> 3;

    float mx = means[g*3+0], my = means[g*3+1], mz = means[g*3+2];
    const float* T = transforms + (size_t)g * 16;
    float mwx = T[0]*mx + T[1]*my + T[2] *mz + T[3];
    float mwy = T[4]*mx + T[5]*my + T[6] *mz + T[7];
    float mwz = T[8]*mx + T[9]*my + T[10]*mz + T[11];

    float qw = rots[g*4+0], qx = rots[g*4+1], qy = rots[g*4+2], qz = rots[g*4+3];
    float qn = rsqrtf(qw*qw + qx*qx + qy*qy + qz*qz);
    qw *= qn; qx *= qn; qy *= qn; qz *= qn;
    float r00 = 1.f-2.f*(qy*qy+qz*qz), r01 = 2.f*(qx*qy-qw*qz), r02 = 2.f*(qx*qz+qw*qy);
    float r10 = 2.f*(qx*qy+qw*qz), r11 = 1.f-2.f*(qx*qx+qz*qz), r12 = 2.f*(qy*qz-qw*qx);
    float r20 = 2.f*(qx*qz-qw*qy), r21 = 2.f*(qy*qz+qw*qx), r22 = 1.f-2.f*(qx*qx+qy*qy);

    float s0, s1, s2;
    if (kp < 6) { s0 = c_fix[kp*3+0]; s1 = c_fix[kp*3+1]; s2 = c_fix[kp*3+2]; }
    else {
        const float* l = g_learn + (size_t)r * 18 + (kp - 6) * 3;
        s0 = l[0]; s1 = l[1]; s2 = l[2];
    }
    float v0 = s0 * scales[g*3+0], v1 = s1 * scales[g*3+1], v2 = s2 * scales[g*3+2];
    float px = r00*v0 + r10*v1 + r20*v2 + mwx;
    float py = r01*v0 + r11*v1 + r21*v2 + mwy;
    float pz = r02*v0 + r12*v1 + r22*v2 + mwz;
    float p0 = proj[0]*px + proj[1]*py + proj[2] *pz + proj[3];
    float p1 = proj[4]*px + proj[5]*py + proj[6] *pz + proj[7];
    float p2 = proj[8]*px + proj[9]*py + proj[10]*pz + proj[11];
    float zz = fmaxf(p2, 1e-5f);
    float u = p0 / zz, v = p1 / zz;
    const float lim = 0.9999f * (float)IMG;
    float xf = fminf(fmaxf(u, 0.f), lim) - 0.5f;
    float yf = fminf(fmaxf(v, 0.f), lim) - 0.5f;
    float fx0 = floorf(xf), fy0 = floorf(yf);
    float wx1 = xf - fx0, wy1 = yf - fy0;
    int x0 = (int)fx0, y0 = (int)fy0;
    int base = (y0 * IMG + x0) * 256;          // byte offset into head's kv plane
    int vx0 = (unsigned)x0       < IMG;
    int vx1 = (unsigned)(x0 + 1) < IMG;
    int vy0 = (unsigned)y0       < IMG;
    int vy1 = (unsigned)(y0 + 1) < IMG;
    int fl = (vy0 & vx0) | ((vy0 & vx1) << 1) | ((vy1 & vx0) << 2) | ((vy1 & vx1) << 3);
    g_pts[id] = make_int4(base, fl, __float_as_int(wx1), __float_as_int(wy1));
}

// ---------------------------------------------------------------------------
// K5: gather_attn — pure gather + softmax + weighted-V.  Block = gaussian,
//     warp = head.  2 points per iteration: lanes 0-15 point 2i, 16-31 point
//     2i+1; each lane holds 4 k + 4 v channels (channels 4l..4l+3).
// ---------------------------------------------------------------------------
__global__ __launch_bounds__(256) void gather_attn()
{
    const int g    = blockIdx.x;
    const int tid  = threadIdx.x;
    const int h    = tid >> 5;
    const int lane = tid & 31;
    const int l    = lane & 15;
    const int half = lane >> 4;

    // q: channels 4l..4l+3 per token (fp32, L2-resident)
    const float* qr = g_q + (size_t)(g * 3) * AD + h * HDIM + l * 4;
    union { float4 f; u64t u[2]; } Q0, Q1, Q2;
    Q0.f = *(const float4*)(qr);
    Q1.f = *(const float4*)(qr + AD);
    Q2.f = *(const float4*)(qr + 2 * AD);

    // 12 precomputed points, staged in lanes 0..11
    int4 pt;
    { int kpl = lane < KPTS ? lane : KPTS - 1;
      pt = g_pts[(size_t)(g * NH + h) * KPTS + kpl]; }

    const char* kvb = (const char*)g_kv + (size_t)h * NPIX * 256 + l * 16;

    float s0v = 0.f, s1v = 0.f, s2v = 0.f;
    u64t o0a = 0ull, o0b = 0ull, o1a = 0ull, o1b = 0ull, o2a = 0ull, o2b = 0ull;

#pragma unroll
    for (int i = 0; i < KPTS / 2; i++) {
        const int src = 2 * i + half;
        int   bb   = __shfl_sync(0xffffffffu, pt.x, src);
        int   bf   = __shfl_sync(0xffffffffu, pt.y, src);
        float wx1  = __int_as_float(__shfl_sync(0xffffffffu, pt.z, src));
        float wy1  = __int_as_float(__shfl_sync(0xffffffffu, pt.w, src));
        float wx0 = 1.f - wx1, wy0 = 1.f - wy1;
        const char* p = kvb + bb;
        uint4 t00 = make_uint4(0,0,0,0), t01 = t00, t10 = t00, t11 = t00;
        if (bf & 1) t00 = *(const uint4*)(p);
        if (bf & 2) t01 = *(const uint4*)(p + 256);
        if (bf & 4) t10 = *(const uint4*)(p + IMG * 256);
        if (bf & 8) t11 = *(const uint4*)(p + IMG * 256 + 256);

        float w00 = wx0*wy0, w01 = wx1*wy0, w10 = wx0*wy1, w11 = wx1*wy1;
        u64t aka = 0ull, akb = 0ull, ava = 0ull, avb = 0ull;
        {
            union { uint4 u; __half2 h2[4]; } c;
            float2 f;
            u64t ws;
            c.u = t00; ws = splat2(w00);
            f = __half22float2(c.h2[0]); aka = ffma2(ws, pk2(f.x, f.y), aka);
            f = __half22float2(c.h2[1]); akb = ffma2(ws, pk2(f.x, f.y), akb);
            f = __half22float2(c.h2[2]); ava = ffma2(ws, pk2(f.x, f.y), ava);
            f = __half22float2(c.h2[3]); avb = ffma2(ws, pk2(f.x, f.y), avb);
            c.u = t01; ws = splat2(w01);
            f = __half22float2(c.h2[0]); aka = ffma2(ws, pk2(f.x, f.y), aka);
            f = __half22float2(c.h2[1]); akb = ffma2(ws, pk2(f.x, f.y), akb);
            f = __half22float2(c.h2[2]); ava = ffma2(ws, pk2(f.x, f.y), ava);
            f = __half22float2(c.h2[3]); avb = ffma2(ws, pk2(f.x, f.y), avb);
            c.u = t10; ws = splat2(w10);
            f = __half22float2(c.h2[0]); aka = ffma2(ws, pk2(f.x, f.y), aka);
            f = __half22float2(c.h2[1]); akb = ffma2(ws, pk2(f.x, f.y), akb);
            f = __half22float2(c.h2[2]); ava = ffma2(ws, pk2(f.x, f.y), ava);
            f = __half22float2(c.h2[3]); avb = ffma2(ws, pk2(f.x, f.y), avb);
            c.u = t11; ws = splat2(w11);
            f = __half22float2(c.h2[0]); aka = ffma2(ws, pk2(f.x, f.y), aka);
            f = __half22float2(c.h2[1]); akb = ffma2(ws, pk2(f.x, f.y), akb);
            f = __half22float2(c.h2[2]); ava = ffma2(ws, pk2(f.x, f.y), ava);
            f = __half22float2(c.h2[3]); avb = ffma2(ws, pk2(f.x, f.y), avb);
        }

        // per-token dots over this half's 64 k-channels (16 lanes x 4 ch)
        float2 p0 = unpk(ffma2(Q0.u[0], aka, fmul2(Q0.u[1], akb)));
        float2 p1 = unpk(ffma2(Q1.u[0], aka, fmul2(Q1.u[1], akb)));
        float2 p2 = unpk(ffma2(Q2.u[0], aka, fmul2(Q2.u[1], akb)));
        float d0 = p0.x + p0.y, d1 = p1.x + p1.y, d2 = p2.x + p2.y;
#pragma unroll
        for (int off = 8; off > 0; off >>= 1) {
            d0 += __shfl_xor_sync(0xffffffffu, d0, off);
            d1 += __shfl_xor_sync(0xffffffffu, d1, off);
            d2 += __shfl_xor_sync(0xffffffffu, d2, off);
        }
        float e0 = __expf(d0 * 0.125f);
        float e1 = __expf(d1 * 0.125f);
        float e2 = __expf(d2 * 0.125f);
        s0v += e0; s1v += e1; s2v += e2;
        u64t e0p = splat2(e0), e1p = splat2(e1), e2p = splat2(e2);
        o0a = ffma2(e0p, ava, o0a); o0b = ffma2(e0p, avb, o0b);
        o1a = ffma2(e1p, ava, o1a); o1b = ffma2(e1p, avb, o1b);
        o2a = ffma2(e2p, ava, o2a); o2b = ffma2(e2p, avb, o2b);
    }

    // combine the two halves (each summed 6 points over identical channels)
    o0a = fadd2(o0a, shflx64(o0a, 16)); o0b = fadd2(o0b, shflx64(o0b, 16));
    o1a = fadd2(o1a, shflx64(o1a, 16)); o1b = fadd2(o1b, shflx64(o1b, 16));
    o2a = fadd2(o2a, shflx64(o2a, 16)); o2b = fadd2(o2b, shflx64(o2b, 16));
    s0v += __shfl_xor_sync(0xffffffffu, s0v, 16);
    s1v += __shfl_xor_sync(0xffffffffu, s1v, 16);
    s2v += __shfl_xor_sync(0xffffffffu, s2v, 16);

    if (half == 0) {
        __half* orow = g_attn + (size_t)(g * 3) * AD + h * HDIM + l * 4;
        u64t i0 = splat2(1.f / s0v), i1 = splat2(1.f / s1v), i2 = splat2(1.f / s2v);
        union { uint2 u; __half2 h2[2]; } cv;
        float2 a, b;
        a = unpk(fmul2(o0a, i0)); b = unpk(fmul2(o0b, i0));
        cv.h2[0] = __floats2half2_rn(a.x, a.y); cv.h2[1] = __floats2half2_rn(b.x, b.y);
        *(uint2*)(orow) = cv.u;
        a = unpk(fmul2(o1a, i1)); b = unpk(fmul2(o1b, i1));
        cv.h2[0] = __floats2half2_rn(a.x, a.y); cv.h2[1] = __floats2half2_rn(b.x, b.y);
        *(uint2*)(orow + AD) = cv.u;
        a = unpk(fmul2(o2a, i2)); b = unpk(fmul2(o2b, i2));
        cv.h2[0] = __floats2half2_rn(a.x, a.y); cv.h2[1] = __floats2half2_rn(b.x, b.y);
        *(uint2*)(orow + 2 * AD) = cv.u;
    }
}

// ---------------------------------------------------------------------------
// K6: out = g_attn(fp16) @ Wout + b_out + features.  M=24576, K=512, N=32.
// ---------------------------------------------------------------------------
__global__ __launch_bounds__(256) void out_gemm(
    const float* __restrict__ Wout, const float* __restrict__ b_out,
    const float* __restrict__ feat, float* __restrict__ out)
{
    const int r0 = blockIdx.x * 64;
    __shared__ float Xs[64][32];
    __shared__ float Ws[32][32];
    const int t = threadIdx.x;
    const int c = t & 31, rb = (t >> 5) * 8;
    float acc[8] = {0.f,0.f,0.f,0.f,0.f,0.f,0.f,0.f};

    for (int k0 = 0; k0 < AD; k0 += 32) {
#pragma unroll
        for (int rep = 0; rep < 8; rep++) {
            int idx = t + rep * 256;
            Xs[idx >> 5][idx & 31] = __half2float(
                g_attn[(size_t)(r0 + (idx >> 5)) * AD + k0 + (idx & 31)]);
        }
#pragma unroll
        for (int rep = 0; rep < 4; rep++) {
            int idx = t + rep * 256;
            Ws[idx >> 5][idx & 31] = Wout[(size_t)(k0 + (idx >> 5)) * GFDIM + (idx & 31)];
        }
        __syncthreads();
#pragma unroll
        for (int kk = 0; kk < 32; kk++) {
            float w = Ws[kk][c];
#pragma unroll
            for (int i = 0; i < 8; i++) acc[i] += Xs[rb + i][kk] * w;
        }
        __syncthreads();
    }
    float b = b_out[c];
#pragma unroll
    for (int i = 0; i < 8; i++) {
        int r = r0 + rb + i;
        out[(size_t)r * GFDIM + c] = acc[i] + b + feat[(size_t)r * GFDIM + c];
    }
}

// ---------------------------------------------------------------------------
extern "C" void kernel_launch(void* const* d_in, const int* in_sizes, int n_in,
                              void* d_out, int out_size)
{
    const float* means      = (const float*)d_in[0];
    const float* scales     = (const float*)d_in[1];
    const float* rotations  = (const float*)d_in[2];
    const float* features   = (const float*)d_in[3];
    const float* transforms = (const float*)d_in[4];
    const float* projection = (const float*)d_in[5];
    const float* image_feat = (const float*)d_in[6];
    const float* Wq         = (const float*)d_in[7];
    const float* Wk         = (const float*)d_in[8];
    const float* Wv         = (const float*)d_in[9];
    const float* W_off      = (const float*)d_in[10];
    const float* b_off      = (const float*)d_in[11];
    const float* Wout       = (const float*)d_in[12];
    const float* b_out      = (const float*)d_in[13];
    float* out = (float*)d_out;

    kv_gemm<<<dim3(NPIX / 64, AD / 128), 256>>>(image_feat, Wk, Wv);
    q_gemm<<<dim3(G_N * 3 / 64, AD / 256), 256>>>(features, Wq);
    sig_gemm<<<NGH / 64, 256>>>(means, transforms, W_off, b_off);
    pointprep<<<NGH * KPTS / 256, 256>>>(means, scales, rotations, transforms,
                                         projection);
    gather_attn<<<G_N, 256>>>();
    out_gemm<<<G_N * 3 / 64, 256>>>(Wout, b_out, features, out);
}

// round 7
// speedup vs baseline: 1.3313x; 1.0563x over previous
#include <cuda_runtime.h>
#include <cuda_fp16.h>

#define G_N   8192
#define NH    8
#define HDIM  64
#define AD    512
#define GFDIM 32
#define CIMG  256
#define IMG   64
#define NPIX  (IMG*IMG)
#define KPTS  12
#define SIGC  9.21f
#define NGH   (G_N * NH)

typedef unsigned long long u64t;

// ---- packed f32x2 helpers ----
__device__ __forceinline__ u64t ffma2(u64t a, u64t b, u64t c) {
    u64t d; asm("fma.rn.f32x2 %0, %1, %2, %3;" : "=l"(d) : "l"(a), "l"(b), "l"(c));
    return d;
}
__device__ __forceinline__ u64t fmul2(u64t a, u64t b) {
    u64t d; asm("mul.rn.f32x2 %0, %1, %2;" : "=l"(d) : "l"(a), "l"(b)); return d;
}
__device__ __forceinline__ u64t fadd2(u64t a, u64t b) {
    u64t d; asm("add.rn.f32x2 %0, %1, %2;" : "=l"(d) : "l"(a), "l"(b)); return d;
}
__device__ __forceinline__ u64t splat2(float x) {
    u64t d; asm("mov.b64 %0, {%1, %1};" : "=l"(d) : "f"(x)); return d;
}
__device__ __forceinline__ u64t pk2(float x, float y) {
    u64t d; asm("mov.b64 %0, {%1, %2};" : "=l"(d) : "f"(x), "f"(y)); return d;
}
__device__ __forceinline__ float2 unpk(u64t a) {
    float2 r; asm("mov.b64 {%0, %1}, %2;" : "=f"(r.x), "=f"(r.y) : "l"(a)); return r;
}
__device__ __forceinline__ u64t shflx64(u64t v, int m) {
    float2 f = unpk(v);
    f.x = __shfl_xor_sync(0xffffffffu, f.x, m);
    f.y = __shfl_xor_sync(0xffffffffu, f.y, m);
    return pk2(f.x, f.y);
}

// Scratch buffers
__device__ __half g_kv[NH * NPIX * 128];     // [h][pix][lane16: k4|v4] 8MB
__device__ float  g_q[G_N * 3 * AD];         // 50MB
__device__ float  g_learn[NGH * 18];         // 4.7MB
__device__ int4   g_pts[NGH * KPTS];         // 12.6MB
__device__ __half g_attn[G_N * 3 * AD];      // 25MB

__constant__ float c_fix[18] = {0,0,0, 1,0,0, 0,1,0, 0,0,1, -1,0,0, 0,-1,0};

// ---------------------------------------------------------------------------
// K1: kv maps -> fp16 g_kv (unchanged from R5)
// ---------------------------------------------------------------------------
__global__ __launch_bounds__(256) void kv_gemm(
    const float* __restrict__ img, const float* __restrict__ Wk,
    const float* __restrict__ Wv)
{
    const int m0 = blockIdx.x * 64;
    const int n0 = blockIdx.y * 128;
    __shared__ float As[16][64];
    __shared__ float Bks[16][128];
    __shared__ float Bvs[16][128];
    const int t  = threadIdx.x;
    const int tx = t & 15, ty = t >> 4;

    u64t ak2[4][4], av2[4][4];
#pragma unroll
    for (int i = 0; i < 4; i++)
#pragma unroll
        for (int j = 0; j < 4; j++) { ak2[i][j] = 0ull; av2[i][j] = 0ull; }

    for (int c0 = 0; c0 < CIMG; c0 += 16) {
        *(float4*)&As[ty][tx * 4] =
            *(const float4*)(img + (size_t)(c0 + ty) * NPIX + m0 + tx * 4);
#pragma unroll
        for (int rep = 0; rep < 2; rep++) {
            int idx = t + rep * 256;
            int nn  = idx >> 2;
            int kk4 = (idx & 3) * 4;
            float4 wk = *(const float4*)(Wk + (size_t)(n0 + nn) * CIMG + c0 + kk4);
            float4 wv = *(const float4*)(Wv + (size_t)(n0 + nn) * CIMG + c0 + kk4);
            Bks[kk4 + 0][nn] = wk.x; Bks[kk4 + 1][nn] = wk.y;
            Bks[kk4 + 2][nn] = wk.z; Bks[kk4 + 3][nn] = wk.w;
            Bvs[kk4 + 0][nn] = wv.x; Bvs[kk4 + 1][nn] = wv.y;
            Bvs[kk4 + 2][nn] = wv.z; Bvs[kk4 + 3][nn] = wv.w;
        }
        __syncthreads();
#pragma unroll
        for (int kk = 0; kk < 16; kk++) {
            float4 a4 = *(float4*)&As[kk][ty * 4];
            ulonglong2 bkl = *(ulonglong2*)&Bks[kk][tx * 4];
            ulonglong2 bkh = *(ulonglong2*)&Bks[kk][tx * 4 + 64];
            ulonglong2 bvl = *(ulonglong2*)&Bvs[kk][tx * 4];
            ulonglong2 bvh = *(ulonglong2*)&Bvs[kk][tx * 4 + 64];
            u64t bk[4] = {bkl.x, bkl.y, bkh.x, bkh.y};
            u64t bv[4] = {bvl.x, bvl.y, bvh.x, bvh.y};
            float a[4] = {a4.x, a4.y, a4.z, a4.w};
#pragma unroll
            for (int i = 0; i < 4; i++) {
                u64t as = splat2(a[i]);
#pragma unroll
                for (int j = 0; j < 4; j++) {
                    ak2[i][j] = ffma2(as, bk[j], ak2[i][j]);
                    av2[i][j] = ffma2(as, bv[j], av2[i][j]);
                }
            }
        }
        __syncthreads();
    }
#pragma unroll
    for (int i = 0; i < 4; i++) {
        int m = m0 + ty * 4 + i;
#pragma unroll
        for (int q = 0; q < 2; q++) {
            int hh = (n0 >> 6) + q;
            __half* dst = g_kv + ((size_t)(hh * NPIX + m)) * 128 + tx * 8;
            float2 k0 = unpk(ak2[i][q*2+0]), k1 = unpk(ak2[i][q*2+1]);
            float2 v0 = unpk(av2[i][q*2+0]), v1 = unpk(av2[i][q*2+1]);
            union { uint4 u; __half2 h2[4]; } p;
            p.h2[0] = __floats2half2_rn(k0.x, k0.y);
            p.h2[1] = __floats2half2_rn(k1.x, k1.y);
            p.h2[2] = __floats2half2_rn(v0.x, v0.y);
            p.h2[3] = __floats2half2_rn(v1.x, v1.y);
            *(uint4*)dst = p.u;
        }
    }
}

// ---------------------------------------------------------------------------
// K2: q = features @ Wq, FFMA2 inner loop.
// ---------------------------------------------------------------------------
__global__ __launch_bounds__(256) void q_gemm(
    const float* __restrict__ feat, const float* __restrict__ Wq)
{
    const int r0 = blockIdx.x * 64;
    const int n0 = blockIdx.y * 256;
    __shared__ float Fs[64][32];
    __shared__ float Ws[32][256];
    const int t = threadIdx.x;
#pragma unroll
    for (int rep = 0; rep < 8; rep++) {
        int idx = t + rep * 256;
        Fs[idx >> 5][idx & 31] = feat[(size_t)(r0 + (idx >> 5)) * GFDIM + (idx & 31)];
    }
#pragma unroll
    for (int rep = 0; rep < 8; rep++) {
        int idx = t + rep * 256;
        int k = idx >> 6, n4 = (idx & 63) << 2;
        *(float4*)&Ws[k][n4] = *(const float4*)(Wq + (size_t)k * AD + n0 + n4);
    }
    __syncthreads();

    const int tc = t & 15, tr = t >> 4;
    u64t acc2[4][8];
#pragma unroll
    for (int i = 0; i < 4; i++)
#pragma unroll
        for (int j = 0; j < 8; j++) acc2[i][j] = 0ull;

#pragma unroll
    for (int k = 0; k < 32; k++) {
        u64t fs[4];
#pragma unroll
        for (int i = 0; i < 4; i++) fs[i] = splat2(Fs[tr * 4 + i][k]);
        u64t w[8];
#pragma unroll
        for (int q = 0; q < 4; q++) {
            ulonglong2 w2 = *(ulonglong2*)&Ws[k][q * 64 + tc * 4];
            w[q*2+0] = w2.x; w[q*2+1] = w2.y;
        }
#pragma unroll
        for (int i = 0; i < 4; i++)
#pragma unroll
            for (int j = 0; j < 8; j++) acc2[i][j] = ffma2(fs[i], w[j], acc2[i][j]);
    }
#pragma unroll
    for (int i = 0; i < 4; i++) {
        int r = r0 + tr * 4 + i;
#pragma unroll
        for (int q = 0; q < 4; q++) {
            float2 a = unpk(acc2[i][q*2+0]), b = unpk(acc2[i][q*2+1]);
            *(float4*)&g_q[(size_t)r * AD + n0 + q * 64 + tc * 4] =
                make_float4(a.x, a.y, b.x, b.y);
        }
    }
}

// ---------------------------------------------------------------------------
// K3: sig_gemm (unchanged from R5)
// ---------------------------------------------------------------------------
__global__ __launch_bounds__(256) void sig_gemm(
    const float* __restrict__ means, const float* __restrict__ transforms,
    const float* __restrict__ W_off, const float* __restrict__ b_off)
{
    const int r0 = blockIdx.x * 64;
    __shared__ float Xs[64][69];
    __shared__ float Ws[67][20];
    __shared__ float bs[20];
    const int t = threadIdx.x;

    for (int idx = t; idx < 64 * 64; idx += 256) {
        int rl = idx >> 6, c = idx & 63;
        int r = r0 + rl, g = r >> 3, h = r & 7;
        const float* q = g_q + (size_t)(g * 3) * AD + h * HDIM + c;
        Xs[rl][3 + c] = (q[0] + q[AD] + q[2 * AD]) * (1.f / 3.f);
    }
    if (t < 64) {
        int r = r0 + t, g = r >> 3;
        float mx = means[g*3], my = means[g*3+1], mz = means[g*3+2];
        const float* T = transforms + (size_t)g * 16;
        Xs[t][0] = T[0]*mx + T[1]*my + T[2] *mz + T[3];
        Xs[t][1] = T[4]*mx + T[5]*my + T[6] *mz + T[7];
        Xs[t][2] = T[8]*mx + T[9]*my + T[10]*mz + T[11];
    }
    for (int idx = t; idx < 67 * 20; idx += 256) {
        int i = idx / 20, o = idx % 20;
        Ws[i][o] = (o < 18) ? W_off[i * 18 + o] : 0.f;
    }
    if (t < 20) bs[t] = (t < 18) ? b_off[t] : 0.f;
    __syncthreads();

    const int rl = t & 63, og = t >> 6;
    const int obase = og * 5;
    float acc[5] = {0.f, 0.f, 0.f, 0.f, 0.f};
    for (int i = 0; i < 67; i++) {
        float x = Xs[rl][i];
#pragma unroll
        for (int u = 0; u < 5; u++) acc[u] += x * Ws[i][obase + u];
    }
    const int on = (og == 3) ? 3 : 5;
    for (int u = 0; u < on; u++) {
        float z = acc[u] + bs[obase + u];
        z = fminf(fmaxf(z, -SIGC), SIGC);
        g_learn[(size_t)(r0 + rl) * 18 + obase + u] = 1.f / (1.f + __expf(-z)) - 0.5f;
    }
}

// ---------------------------------------------------------------------------
// K4: pointprep (unchanged from R5)
// ---------------------------------------------------------------------------
__global__ __launch_bounds__(256) void pointprep(
    const float* __restrict__ means, const float* __restrict__ scales,
    const float* __restrict__ rots, const float* __restrict__ transforms,
    const float* __restrict__ proj)
{
    int id = blockIdx.x * 256 + threadIdx.x;
    int kp = id % KPTS;
    int r  = id / KPTS;
    int g  = r >> 3;

    float mx = means[g*3+0], my = means[g*3+1], mz = means[g*3+2];
    const float* T = transforms + (size_t)g * 16;
    float mwx = T[0]*mx + T[1]*my + T[2] *mz + T[3];
    float mwy = T[4]*mx + T[5]*my + T[6] *mz + T[7];
    float mwz = T[8]*mx + T[9]*my + T[10]*mz + T[11];

    float qw = rots[g*4+0], qx = rots[g*4+1], qy = rots[g*4+2], qz = rots[g*4+3];
    float qn = rsqrtf(qw*qw + qx*qx + qy*qy + qz*qz);
    qw *= qn; qx *= qn; qy *= qn; qz *= qn;
    float r00 = 1.f-2.f*(qy*qy+qz*qz), r01 = 2.f*(qx*qy-qw*qz), r02 = 2.f*(qx*qz+qw*qy);
    float r10 = 2.f*(qx*qy+qw*qz), r11 = 1.f-2.f*(qx*qx+qz*qz), r12 = 2.f*(qy*qz-qw*qx);
    float r20 = 2.f*(qx*qz-qw*qy), r21 = 2.f*(qy*qz+qw*qx), r22 = 1.f-2.f*(qx*qx+qy*qy);

    float s0, s1, s2;
    if (kp < 6) { s0 = c_fix[kp*3+0]; s1 = c_fix[kp*3+1]; s2 = c_fix[kp*3+2]; }
    else {
        const float* l = g_learn + (size_t)r * 18 + (kp - 6) * 3;
        s0 = l[0]; s1 = l[1]; s2 = l[2];
    }
    float v0 = s0 * scales[g*3+0], v1 = s1 * scales[g*3+1], v2 = s2 * scales[g*3+2];
    float px = r00*v0 + r10*v1 + r20*v2 + mwx;
    float py = r01*v0 + r11*v1 + r21*v2 + mwy;
    float pz = r02*v0 + r12*v1 + r22*v2 + mwz;
    float p0 = proj[0]*px + proj[1]*py + proj[2] *pz + proj[3];
    float p1 = proj[4]*px + proj[5]*py + proj[6] *pz + proj[7];
    float p2 = proj[8]*px + proj[9]*py + proj[10]*pz + proj[11];
    float zz = fmaxf(p2, 1e-5f);
    float u = p0 / zz, v = p1 / zz;
    const float lim = 0.9999f * (float)IMG;
    float xf = fminf(fmaxf(u, 0.f), lim) - 0.5f;
    float yf = fminf(fmaxf(v, 0.f), lim) - 0.5f;
    float fx0 = floorf(xf), fy0 = floorf(yf);
    float wx1 = xf - fx0, wy1 = yf - fy0;
    int x0 = (int)fx0, y0 = (int)fy0;
    int base = (y0 * IMG + x0) * 256;
    int vx0 = (unsigned)x0       < IMG;
    int vx1 = (unsigned)(x0 + 1) < IMG;
    int vy0 = (unsigned)y0       < IMG;
    int vy1 = (unsigned)(y0 + 1) < IMG;
    int fl = (vy0 & vx0) | ((vy0 & vx1) << 1) | ((vy1 & vx0) << 2) | ((vy1 & vx1) << 3);
    g_pts[id] = make_int4(base, fl, __float_as_int(wx1), __float_as_int(wy1));
}

// ---------------------------------------------------------------------------
// K5: gather_attn v2 — HFMA2 bilinear + depth-2 software pipeline.
// ---------------------------------------------------------------------------
__global__ __launch_bounds__(256) void gather_attn()
{
    const int g    = blockIdx.x;
    const int tid  = threadIdx.x;
    const int h    = tid >> 5;
    const int lane = tid & 31;
    const int l    = lane & 15;
    const int half = lane >> 4;

    const float* qr = g_q + (size_t)(g * 3) * AD + h * HDIM + l * 4;
    union { float4 f; u64t u[2]; } Q0, Q1, Q2;
    Q0.f = *(const float4*)(qr);
    Q1.f = *(const float4*)(qr + AD);
    Q2.f = *(const float4*)(qr + 2 * AD);

    int4 pt;
    { int kpl = lane < KPTS ? lane : KPTS - 1;
      pt = g_pts[(size_t)(g * NH + h) * KPTS + kpl]; }

    const char* kvb = (const char*)g_kv + (size_t)h * NPIX * 256 + l * 16;

    float s0v = 0.f, s1v = 0.f, s2v = 0.f;
    u64t o0a = 0ull, o0b = 0ull, o1a = 0ull, o1b = 0ull, o2a = 0ull, o2b = 0ull;

    // pipeline prologue: fetch iteration 0
    uint4 T0, T1, T2, T3;
    float cwx1, cwy1;
    {
        int   bb = __shfl_sync(0xffffffffu, pt.x, half);
        int   bf = __shfl_sync(0xffffffffu, pt.y, half);
        cwx1 = __int_as_float(__shfl_sync(0xffffffffu, pt.z, half));
        cwy1 = __int_as_float(__shfl_sync(0xffffffffu, pt.w, half));
        const char* p = kvb + bb;
        T0 = T1 = T2 = T3 = make_uint4(0, 0, 0, 0);
        if (bf & 1) T0 = *(const uint4*)(p);
        if (bf & 2) T1 = *(const uint4*)(p + 256);
        if (bf & 4) T2 = *(const uint4*)(p + IMG * 256);
        if (bf & 8) T3 = *(const uint4*)(p + IMG * 256 + 256);
    }

#pragma unroll
    for (int i = 0; i < KPTS / 2; i++) {
        uint4 N0, N1, N2, N3;
        float nwx1 = 0.f, nwy1 = 0.f;
        N0 = N1 = N2 = N3 = make_uint4(0, 0, 0, 0);
        if (i < KPTS / 2 - 1) {     // prefetch next iteration
            int src = 2 * (i + 1) + half;
            int bb = __shfl_sync(0xffffffffu, pt.x, src);
            int bf = __shfl_sync(0xffffffffu, pt.y, src);
            nwx1 = __int_as_float(__shfl_sync(0xffffffffu, pt.z, src));
            nwy1 = __int_as_float(__shfl_sync(0xffffffffu, pt.w, src));
            const char* p = kvb + bb;
            if (bf & 1) N0 = *(const uint4*)(p);
            if (bf & 2) N1 = *(const uint4*)(p + 256);
            if (bf & 4) N2 = *(const uint4*)(p + IMG * 256);
            if (bf & 8) N3 = *(const uint4*)(p + IMG * 256 + 256);
        }

        // ---- bilinear in half2 (HFMA2) ----
        float wx0 = 1.f - cwx1, wy0 = 1.f - cwy1;
        __half2 hw00 = __float2half2_rn(wx0  * wy0);
        __half2 hw01 = __float2half2_rn(cwx1 * wy0);
        __half2 hw10 = __float2half2_rn(wx0  * cwy1);
        __half2 hw11 = __float2half2_rn(cwx1 * cwy1);
        union { uint4 u; __half2 h2[4]; } A, B, C, D;
        A.u = T0; B.u = T1; C.u = T2; D.u = T3;
        __half2 hk0 = __hfma2(hw00, A.h2[0], __hfma2(hw01, B.h2[0],
                      __hfma2(hw10, C.h2[0], __hmul2(hw11, D.h2[0]))));
        __half2 hk1 = __hfma2(hw00, A.h2[1], __hfma2(hw01, B.h2[1],
                      __hfma2(hw10, C.h2[1], __hmul2(hw11, D.h2[1]))));
        __half2 hv0 = __hfma2(hw00, A.h2[2], __hfma2(hw01, B.h2[2],
                      __hfma2(hw10, C.h2[2], __hmul2(hw11, D.h2[2]))));
        __half2 hv1 = __hfma2(hw00, A.h2[3], __hfma2(hw01, B.h2[3],
                      __hfma2(hw10, C.h2[3], __hmul2(hw11, D.h2[3]))));
        float2 kf0 = __half22float2(hk0), kf1 = __half22float2(hk1);
        float2 vf0 = __half22float2(hv0), vf1 = __half22float2(hv1);
        u64t aka = pk2(kf0.x, kf0.y), akb = pk2(kf1.x, kf1.y);
        u64t ava = pk2(vf0.x, vf0.y), avb = pk2(vf1.x, vf1.y);

        // ---- dots + 16-lane reduce ----
        float2 p0 = unpk(ffma2(Q0.u[0], aka, fmul2(Q0.u[1], akb)));
        float2 p1 = unpk(ffma2(Q1.u[0], aka, fmul2(Q1.u[1], akb)));
        float2 p2 = unpk(ffma2(Q2.u[0], aka, fmul2(Q2.u[1], akb)));
        float d0 = p0.x + p0.y, d1 = p1.x + p1.y, d2 = p2.x + p2.y;
#pragma unroll
        for (int off = 8; off > 0; off >>= 1) {
            d0 += __shfl_xor_sync(0xffffffffu, d0, off);
            d1 += __shfl_xor_sync(0xffffffffu, d1, off);
            d2 += __shfl_xor_sync(0xffffffffu, d2, off);
        }
        float e0 = __expf(d0 * 0.125f);
        float e1 = __expf(d1 * 0.125f);
        float e2 = __expf(d2 * 0.125f);
        s0v += e0; s1v += e1; s2v += e2;
        u64t e0p = splat2(e0), e1p = splat2(e1), e2p = splat2(e2);
        o0a = ffma2(e0p, ava, o0a); o0b = ffma2(e0p, avb, o0b);
        o1a = ffma2(e1p, ava, o1a); o1b = ffma2(e1p, avb, o1b);
        o2a = ffma2(e2p, ava, o2a); o2b = ffma2(e2p, avb, o2b);

        T0 = N0; T1 = N1; T2 = N2; T3 = N3;
        cwx1 = nwx1; cwy1 = nwy1;
    }

    // combine halves
    o0a = fadd2(o0a, shflx64(o0a, 16)); o0b = fadd2(o0b, shflx64(o0b, 16));
    o1a = fadd2(o1a, shflx64(o1a, 16)); o1b = fadd2(o1b, shflx64(o1b, 16));
    o2a = fadd2(o2a, shflx64(o2a, 16)); o2b = fadd2(o2b, shflx64(o2b, 16));
    s0v += __shfl_xor_sync(0xffffffffu, s0v, 16);
    s1v += __shfl_xor_sync(0xffffffffu, s1v, 16);
    s2v += __shfl_xor_sync(0xffffffffu, s2v, 16);

    if (half == 0) {
        __half* orow = g_attn + (size_t)(g * 3) * AD + h * HDIM + l * 4;
        u64t i0 = splat2(1.f / s0v), i1 = splat2(1.f / s1v), i2 = splat2(1.f / s2v);
        union { uint2 u; __half2 h2[2]; } cv;
        float2 a, b;
        a = unpk(fmul2(o0a, i0)); b = unpk(fmul2(o0b, i0));
        cv.h2[0] = __floats2half2_rn(a.x, a.y); cv.h2[1] = __floats2half2_rn(b.x, b.y);
        *(uint2*)(orow) = cv.u;
        a = unpk(fmul2(o1a, i1)); b = unpk(fmul2(o1b, i1));
        cv.h2[0] = __floats2half2_rn(a.x, a.y); cv.h2[1] = __floats2half2_rn(b.x, b.y);
        *(uint2*)(orow + AD) = cv.u;
        a = unpk(fmul2(o2a, i2)); b = unpk(fmul2(o2b, i2));
        cv.h2[0] = __floats2half2_rn(a.x, a.y); cv.h2[1] = __floats2half2_rn(b.x, b.y);
        *(uint2*)(orow + 2 * AD) = cv.u;
    }
}

// ---------------------------------------------------------------------------
// K6: out = g_attn(fp16) @ Wout + b_out + features.  FFMA2, k-major Xs.
// ---------------------------------------------------------------------------
__global__ __launch_bounds__(256) void out_gemm(
    const float* __restrict__ Wout, const float* __restrict__ b_out,
    const float* __restrict__ feat, float* __restrict__ out)
{
    const int r0 = blockIdx.x * 64;
    __shared__ float Xs[32][66];      // k-major, stride 66 (align 8B, mild conflicts)
    __shared__ float Ws[32][32];
    const int t = threadIdx.x;
    const int c = t & 31, rb = (t >> 5) * 8;
    u64t acc2[4] = {0ull, 0ull, 0ull, 0ull};

    for (int k0 = 0; k0 < AD; k0 += 32) {
#pragma unroll
        for (int rep = 0; rep < 8; rep++) {
            int idx = t + rep * 256;
            int row = idx >> 5, kc = idx & 31;
            Xs[kc][row] = __half2float(
                g_attn[(size_t)(r0 + row) * AD + k0 + kc]);
        }
#pragma unroll
        for (int rep = 0; rep < 4; rep++) {
            int idx = t + rep * 256;
            Ws[idx >> 5][idx & 31] = Wout[(size_t)(k0 + (idx >> 5)) * GFDIM + (idx & 31)];
        }
        __syncthreads();
#pragma unroll
        for (int kk = 0; kk < 32; kk++) {
            u64t w = splat2(Ws[kk][c]);
#pragma unroll
            for (int i = 0; i < 4; i++)
                acc2[i] = ffma2(w, *(const u64t*)&Xs[kk][rb + 2 * i], acc2[i]);
        }
        __syncthreads();
    }
    float b = b_out[c];
#pragma unroll
    for (int i = 0; i < 4; i++) {
        float2 r = unpk(acc2[i]);
        int row0 = r0 + rb + 2 * i;
        out[(size_t)row0 * GFDIM + c]       = r.x + b + feat[(size_t)row0 * GFDIM + c];
        out[(size_t)(row0 + 1) * GFDIM + c] = r.y + b + feat[(size_t)(row0 + 1) * GFDIM + c];
    }
}

// ---------------------------------------------------------------------------
extern "C" void kernel_launch(void* const* d_in, const int* in_sizes, int n_in,
                              void* d_out, int out_size)
{
    const float* means      = (const float*)d_in[0];
    const float* scales     = (const float*)d_in[1];
    const float* rotations  = (const float*)d_in[2];
    const float* features   = (const float*)d_in[3];
    const float* transforms = (const float*)d_in[4];
    const float* projection = (const float*)d_in[5];
    const float* image_feat = (const float*)d_in[6];
    const float* Wq         = (const float*)d_in[7];
    const float* Wk         = (const float*)d_in[8];
    const float* Wv         = (const float*)d_in[9];
    const float* W_off      = (const float*)d_in[10];
    const float* b_off      = (const float*)d_in[11];
    const float* Wout       = (const float*)d_in[12];
    const float* b_out      = (const float*)d_in[13];
    float* out = (float*)d_out;

    kv_gemm<<<dim3(NPIX / 64, AD / 128), 256>>>(image_feat, Wk, Wv);
    q_gemm<<<dim3(G_N * 3 / 64, AD / 256), 256>>>(features, Wq);
    sig_gemm<<<NGH / 64, 256>>>(means, transforms, W_off, b_off);
    pointprep<<<NGH * KPTS / 256, 256>>>(means, scales, rotations, transforms,
                                         projection);
    gather_attn<<<G_N, 256>>>();
    out_gemm<<<G_N * 3 / 64, 256>>>(Wout, b_out, features, out);
}

// round 9
// speedup vs baseline: 1.3661x; 1.0262x over previous
#include <cuda_runtime.h>
#include <cuda_fp16.h>

#define G_N   8192
#define NH    8
#define HDIM  64
#define AD    512
#define GFDIM 32
#define CIMG  256
#define IMG   64
#define NPIX  (IMG*IMG)
#define KPTS  12
#define SIGC  9.21f
#define NGH   (G_N * NH)

typedef unsigned long long u64t;

// ---- packed f32x2 helpers ----
__device__ __forceinline__ u64t ffma2(u64t a, u64t b, u64t c) {
    u64t d; asm("fma.rn.f32x2 %0, %1, %2, %3;" : "=l"(d) : "l"(a), "l"(b), "l"(c));
    return d;
}
__device__ __forceinline__ u64t fmul2(u64t a, u64t b) {
    u64t d; asm("mul.rn.f32x2 %0, %1, %2;" : "=l"(d) : "l"(a), "l"(b)); return d;
}
__device__ __forceinline__ u64t fadd2(u64t a, u64t b) {
    u64t d; asm("add.rn.f32x2 %0, %1, %2;" : "=l"(d) : "l"(a), "l"(b)); return d;
}
__device__ __forceinline__ u64t splat2(float x) {
    u64t d; asm("mov.b64 %0, {%1, %1};" : "=l"(d) : "f"(x)); return d;
}
__device__ __forceinline__ u64t pk2(float x, float y) {
    u64t d; asm("mov.b64 %0, {%1, %2};" : "=l"(d) : "f"(x), "f"(y)); return d;
}
__device__ __forceinline__ float2 unpk(u64t a) {
    float2 r; asm("mov.b64 {%0, %1}, %2;" : "=f"(r.x), "=f"(r.y) : "l"(a)); return r;
}
__device__ __forceinline__ u64t shflx64(u64t v, int m) {
    float2 f = unpk(v);
    f.x = __shfl_xor_sync(0xffffffffu, f.x, m);
    f.y = __shfl_xor_sync(0xffffffffu, f.y, m);
    return pk2(f.x, f.y);
}

// Scratch buffers
__device__ __half g_kv[NH * NPIX * 128];     // [h][pix][lane16: k4|v4] 8MB
__device__ float  g_q[G_N * 3 * AD];         // 50MB
__device__ int4   g_pts[NGH * KPTS];         // 12.6MB
__device__ __half g_attn[G_N * 3 * AD];      // 25MB

__constant__ float c_fix[18] = {0,0,0, 1,0,0, 0,1,0, 0,0,1, -1,0,0, 0,-1,0};

// ---------------------------------------------------------------------------
// K1: kv maps -> fp16 g_kv (unchanged)
// ---------------------------------------------------------------------------
__global__ __launch_bounds__(256) void kv_gemm(
    const float* __restrict__ img, const float* __restrict__ Wk,
    const float* __restrict__ Wv)
{
    const int m0 = blockIdx.x * 64;
    const int n0 = blockIdx.y * 128;
    __shared__ float As[16][64];
    __shared__ float Bks[16][128];
    __shared__ float Bvs[16][128];
    const int t  = threadIdx.x;
    const int tx = t & 15, ty = t >> 4;

    u64t ak2[4][4], av2[4][4];
#pragma unroll
    for (int i = 0; i < 4; i++)
#pragma unroll
        for (int j = 0; j < 4; j++) { ak2[i][j] = 0ull; av2[i][j] = 0ull; }

    for (int c0 = 0; c0 < CIMG; c0 += 16) {
        *(float4*)&As[ty][tx * 4] =
            *(const float4*)(img + (size_t)(c0 + ty) * NPIX + m0 + tx * 4);
#pragma unroll
        for (int rep = 0; rep < 2; rep++) {
            int idx = t + rep * 256;
            int nn  = idx >> 2;
            int kk4 = (idx & 3) * 4;
            float4 wk = *(const float4*)(Wk + (size_t)(n0 + nn) * CIMG + c0 + kk4);
            float4 wv = *(const float4*)(Wv + (size_t)(n0 + nn) * CIMG + c0 + kk4);
            Bks[kk4 + 0][nn] = wk.x; Bks[kk4 + 1][nn] = wk.y;
            Bks[kk4 + 2][nn] = wk.z; Bks[kk4 + 3][nn] = wk.w;
            Bvs[kk4 + 0][nn] = wv.x; Bvs[kk4 + 1][nn] = wv.y;
            Bvs[kk4 + 2][nn] = wv.z; Bvs[kk4 + 3][nn] = wv.w;
        }
        __syncthreads();
#pragma unroll
        for (int kk = 0; kk < 16; kk++) {
            float4 a4 = *(float4*)&As[kk][ty * 4];
            ulonglong2 bkl = *(ulonglong2*)&Bks[kk][tx * 4];
            ulonglong2 bkh = *(ulonglong2*)&Bks[kk][tx * 4 + 64];
            ulonglong2 bvl = *(ulonglong2*)&Bvs[kk][tx * 4];
            ulonglong2 bvh = *(ulonglong2*)&Bvs[kk][tx * 4 + 64];
            u64t bk[4] = {bkl.x, bkl.y, bkh.x, bkh.y};
            u64t bv[4] = {bvl.x, bvl.y, bvh.x, bvh.y};
            float a[4] = {a4.x, a4.y, a4.z, a4.w};
#pragma unroll
            for (int i = 0; i < 4; i++) {
                u64t as = splat2(a[i]);
#pragma unroll
                for (int j = 0; j < 4; j++) {
                    ak2[i][j] = ffma2(as, bk[j], ak2[i][j]);
                    av2[i][j] = ffma2(as, bv[j], av2[i][j]);
                }
            }
        }
        __syncthreads();
    }
#pragma unroll
    for (int i = 0; i < 4; i++) {
        int m = m0 + ty * 4 + i;
#pragma unroll
        for (int q = 0; q < 2; q++) {
            int hh = (n0 >> 6) + q;
            __half* dst = g_kv + ((size_t)(hh * NPIX + m)) * 128 + tx * 8;
            float2 k0 = unpk(ak2[i][q*2+0]), k1 = unpk(ak2[i][q*2+1]);
            float2 v0 = unpk(av2[i][q*2+0]), v1 = unpk(av2[i][q*2+1]);
            union { uint4 u; __half2 h2[4]; } p;
            p.h2[0] = __floats2half2_rn(k0.x, k0.y);
            p.h2[1] = __floats2half2_rn(k1.x, k1.y);
            p.h2[2] = __floats2half2_rn(v0.x, v0.y);
            p.h2[3] = __floats2half2_rn(v1.x, v1.y);
            *(uint4*)dst = p.u;
        }
    }
}

// ---------------------------------------------------------------------------
// K2: q = features @ Wq, FFMA2 inner loop (unchanged)
// ---------------------------------------------------------------------------
__global__ __launch_bounds__(256) void q_gemm(
    const float* __restrict__ feat, const float* __restrict__ Wq)
{
    const int r0 = blockIdx.x * 64;
    const int n0 = blockIdx.y * 256;
    __shared__ float Fs[64][32];
    __shared__ float Ws[32][256];
    const int t = threadIdx.x;
#pragma unroll
    for (int rep = 0; rep < 8; rep++) {
        int idx = t + rep * 256;
        Fs[idx >> 5][idx & 31] = feat[(size_t)(r0 + (idx >> 5)) * GFDIM + (idx & 31)];
    }
#pragma unroll
    for (int rep = 0; rep < 8; rep++) {
        int idx = t + rep * 256;
        int k = idx >> 6, n4 = (idx & 63) << 2;
        *(float4*)&Ws[k][n4] = *(const float4*)(Wq + (size_t)k * AD + n0 + n4);
    }
    __syncthreads();

    const int tc = t & 15, tr = t >> 4;
    u64t acc2[4][8];
#pragma unroll
    for (int i = 0; i < 4; i++)
#pragma unroll
        for (int j = 0; j < 8; j++) acc2[i][j] = 0ull;

#pragma unroll
    for (int k = 0; k < 32; k++) {
        u64t fs[4];
#pragma unroll
        for (int i = 0; i < 4; i++) fs[i] = splat2(Fs[tr * 4 + i][k]);
        u64t w[8];
#pragma unroll
        for (int q = 0; q < 4; q++) {
            ulonglong2 w2 = *(ulonglong2*)&Ws[k][q * 64 + tc * 4];
            w[q*2+0] = w2.x; w[q*2+1] = w2.y;
        }
#pragma unroll
        for (int i = 0; i < 4; i++)
#pragma unroll
            for (int j = 0; j < 8; j++) acc2[i][j] = ffma2(fs[i], w[j], acc2[i][j]);
    }
#pragma unroll
    for (int i = 0; i < 4; i++) {
        int r = r0 + tr * 4 + i;
#pragma unroll
        for (int q = 0; q < 4; q++) {
            float2 a = unpk(acc2[i][q*2+0]), b = unpk(acc2[i][q*2+1]);
            *(float4*)&g_q[(size_t)r * AD + n0 + q * 64 + tc * 4] =
                make_float4(a.x, a.y, b.x, b.y);
        }
    }
}

// ---------------------------------------------------------------------------
// K3: sigpp — fused OffsetNet GEMM + point projection.
//   Block = 64 rows (8 gaussians x 8 heads).  Phase 1: sigmoid outputs into
//   smem.  Phase 2: 768 sample points (3 per thread) -> g_pts.
// ---------------------------------------------------------------------------
__global__ __launch_bounds__(256) void sigpp(
    const float* __restrict__ means, const float* __restrict__ scales,
    const float* __restrict__ rots, const float* __restrict__ transforms,
    const float* __restrict__ proj, const float* __restrict__ W_off,
    const float* __restrict__ b_off)
{
    const int r0 = blockIdx.x * 64;
    __shared__ float Xs[64][69];      // [row][0..2 mw, 3..66 qmean]
    __shared__ float Ws[67][20];
    __shared__ float bs[20];
    __shared__ float sh_learn[64][18];
    __shared__ float sh_rot[8][9];    // per local gaussian
    __shared__ float sh_scl[8][3];
    __shared__ float sh_proj[12];
    const int t = threadIdx.x;

    // ---- phase 1 inputs ----
    for (int idx = t; idx < 64 * 64; idx += 256) {
        int rl = idx >> 6, c = idx & 63;
        int r = r0 + rl, g = r >> 3, h = r & 7;
        const float* q = g_q + (size_t)(g * 3) * AD + h * HDIM + c;
        Xs[rl][3 + c] = (q[0] + q[AD] + q[2 * AD]) * (1.f / 3.f);
    }
    if (t < 64) {
        int r = r0 + t, g = r >> 3;
        float mx = means[g*3], my = means[g*3+1], mz = means[g*3+2];
        const float* T = transforms + (size_t)g * 16;
        Xs[t][0] = T[0]*mx + T[1]*my + T[2] *mz + T[3];
        Xs[t][1] = T[4]*mx + T[5]*my + T[6] *mz + T[7];
        Xs[t][2] = T[8]*mx + T[9]*my + T[10]*mz + T[11];
    }
    for (int idx = t; idx < 67 * 20; idx += 256) {
        int i = idx / 20, o = idx % 20;
        Ws[i][o] = (o < 18) ? W_off[i * 18 + o] : 0.f;
    }
    if (t < 20) bs[t] = (t < 18) ? b_off[t] : 0.f;
    if (t < 12) sh_proj[t] = proj[t];
    if (t >= 32 && t < 40) {          // per-gaussian rot + scale
        int gl = t - 32, g = (r0 >> 3) + gl;
        float qw = rots[g*4+0], qx = rots[g*4+1], qy = rots[g*4+2], qz = rots[g*4+3];
        float qn = rsqrtf(qw*qw + qx*qx + qy*qy + qz*qz);
        qw *= qn; qx *= qn; qy *= qn; qz *= qn;
        sh_rot[gl][0] = 1.f-2.f*(qy*qy+qz*qz); sh_rot[gl][1] = 2.f*(qx*qy-qw*qz);
        sh_rot[gl][2] = 2.f*(qx*qz+qw*qy);     sh_rot[gl][3] = 2.f*(qx*qy+qw*qz);
        sh_rot[gl][4] = 1.f-2.f*(qx*qx+qz*qz); sh_rot[gl][5] = 2.f*(qy*qz-qw*qx);
        sh_rot[gl][6] = 2.f*(qx*qz-qw*qy);     sh_rot[gl][7] = 2.f*(qy*qz+qw*qx);
        sh_rot[gl][8] = 1.f-2.f*(qx*qx+qy*qy);
        sh_scl[gl][0] = scales[g*3+0];
        sh_scl[gl][1] = scales[g*3+1];
        sh_scl[gl][2] = scales[g*3+2];
    }
    __syncthreads();

    // ---- phase 1: [64 x 67] @ [67 x 18] + sigmoid ----
    {
        const int rl = t & 63, og = t >> 6;
        const int obase = og * 5;
        float acc[5] = {0.f, 0.f, 0.f, 0.f, 0.f};
        for (int i = 0; i < 67; i++) {
            float x = Xs[rl][i];
#pragma unroll
            for (int u = 0; u < 5; u++) acc[u] += x * Ws[i][obase + u];
        }
        const int on = (og == 3) ? 3 : 5;
        for (int u = 0; u < on; u++) {
            float z = acc[u] + bs[obase + u];
            z = fminf(fmaxf(z, -SIGC), SIGC);
            sh_learn[rl][obase + u] = 1.f / (1.f + __expf(-z)) - 0.5f;
        }
    }
    __syncthreads();

    // ---- phase 2: 768 points, 3 per thread ----
#pragma unroll
    for (int it = 0; it < 3; it++) {
        int id = t + it * 256;
        int rl = id / KPTS, kp = id - rl * KPTS;
        int gl = rl >> 3;
        float s0, s1, s2;
        if (kp < 6) { s0 = c_fix[kp*3+0]; s1 = c_fix[kp*3+1]; s2 = c_fix[kp*3+2]; }
        else { const float* lp = &sh_learn[rl][(kp - 6) * 3];
               s0 = lp[0]; s1 = lp[1]; s2 = lp[2]; }
        float v0 = s0 * sh_scl[gl][0], v1 = s1 * sh_scl[gl][1], v2 = s2 * sh_scl[gl][2];
        const float* R = sh_rot[gl];
        float px = R[0]*v0 + R[3]*v1 + R[6]*v2 + Xs[rl][0];   // R^T v + mw
        float py = R[1]*v0 + R[4]*v1 + R[7]*v2 + Xs[rl][1];
        float pz = R[2]*v0 + R[5]*v1 + R[8]*v2 + Xs[rl][2];
        float p0 = sh_proj[0]*px + sh_proj[1]*py + sh_proj[2] *pz + sh_proj[3];
        float p1 = sh_proj[4]*px + sh_proj[5]*py + sh_proj[6] *pz + sh_proj[7];
        float p2 = sh_proj[8]*px + sh_proj[9]*py + sh_proj[10]*pz + sh_proj[11];
        float zz = fmaxf(p2, 1e-5f);
        float u = p0 / zz, v = p1 / zz;
        const float lim = 0.9999f * (float)IMG;
        float xf = fminf(fmaxf(u, 0.f), lim) - 0.5f;
        float yf = fminf(fmaxf(v, 0.f), lim) - 0.5f;
        float fx0 = floorf(xf), fy0 = floorf(yf);
        float wx1 = xf - fx0, wy1 = yf - fy0;
        int x0 = (int)fx0, y0 = (int)fy0;
        int base = (y0 * IMG + x0) * 256;
        int vx0 = (unsigned)x0       < IMG;
        int vx1 = (unsigned)(x0 + 1) < IMG;
        int vy0 = (unsigned)y0       < IMG;
        int vy1 = (unsigned)(y0 + 1) < IMG;
        int fl = (vy0 & vx0) | ((vy0 & vx1) << 1) | ((vy1 & vx0) << 2) | ((vy1 & vx1) << 3);
        g_pts[(size_t)(r0 + rl) * KPTS + kp] =
            make_int4(base, fl, __float_as_int(wx1), __float_as_int(wy1));
    }
}

// ---------------------------------------------------------------------------
// K4: gather_attn (unchanged from R7) — now the 4th launch for ncu capture.
// ---------------------------------------------------------------------------
__global__ __launch_bounds__(256) void gather_attn()
{
    const int g    = blockIdx.x;
    const int tid  = threadIdx.x;
    const int h    = tid >> 5;
    const int lane = tid & 31;
    const int l    = lane & 15;
    const int half = lane >> 4;

    const float* qr = g_q + (size_t)(g * 3) * AD + h * HDIM + l * 4;
    union { float4 f; u64t u[2]; } Q0, Q1, Q2;
    Q0.f = *(const float4*)(qr);
    Q1.f = *(const float4*)(qr + AD);
    Q2.f = *(const float4*)(qr + 2 * AD);

    int4 pt;
    { int kpl = lane < KPTS ? lane : KPTS - 1;
      pt = g_pts[(size_t)(g * NH + h) * KPTS + kpl]; }

    const char* kvb = (const char*)g_kv + (size_t)h * NPIX * 256 + l * 16;

    float s0v = 0.f, s1v = 0.f, s2v = 0.f;
    u64t o0a = 0ull, o0b = 0ull, o1a = 0ull, o1b = 0ull, o2a = 0ull, o2b = 0ull;

    uint4 T0, T1, T2, T3;
    float cwx1, cwy1;
    {
        int   bb = __shfl_sync(0xffffffffu, pt.x, half);
        int   bf = __shfl_sync(0xffffffffu, pt.y, half);
        cwx1 = __int_as_float(__shfl_sync(0xffffffffu, pt.z, half));
        cwy1 = __int_as_float(__shfl_sync(0xffffffffu, pt.w, half));
        const char* p = kvb + bb;
        T0 = T1 = T2 = T3 = make_uint4(0, 0, 0, 0);
        if (bf & 1) T0 = *(const uint4*)(p);
        if (bf & 2) T1 = *(const uint4*)(p + 256);
        if (bf & 4) T2 = *(const uint4*)(p + IMG * 256);
        if (bf & 8) T3 = *(const uint4*)(p + IMG * 256 + 256);
    }

#pragma unroll
    for (int i = 0; i < KPTS / 2; i++) {
        uint4 N0, N1, N2, N3;
        float nwx1 = 0.f, nwy1 = 0.f;
        N0 = N1 = N2 = N3 = make_uint4(0, 0, 0, 0);
        if (i < KPTS / 2 - 1) {
            int src = 2 * (i + 1) + half;
            int bb = __shfl_sync(0xffffffffu, pt.x, src);
            int bf = __shfl_sync(0xffffffffu, pt.y, src);
            nwx1 = __int_as_float(__shfl_sync(0xffffffffu, pt.z, src));
            nwy1 = __int_as_float(__shfl_sync(0xffffffffu, pt.w, src));
            const char* p = kvb + bb;
            if (bf & 1) N0 = *(const uint4*)(p);
            if (bf & 2) N1 = *(const uint4*)(p + 256);
            if (bf & 4) N2 = *(const uint4*)(p + IMG * 256);
            if (bf & 8) N3 = *(const uint4*)(p + IMG * 256 + 256);
        }

        float wx0 = 1.f - cwx1, wy0 = 1.f - cwy1;
        __half2 hw00 = __float2half2_rn(wx0  * wy0);
        __half2 hw01 = __float2half2_rn(cwx1 * wy0);
        __half2 hw10 = __float2half2_rn(wx0  * cwy1);
        __half2 hw11 = __float2half2_rn(cwx1 * cwy1);
        union { uint4 u; __half2 h2[4]; } A, B, C, D;
        A.u = T0; B.u = T1; C.u = T2; D.u = T3;
        __half2 hk0 = __hfma2(hw00, A.h2[0], __hfma2(hw01, B.h2[0],
                      __hfma2(hw10, C.h2[0], __hmul2(hw11, D.h2[0]))));
        __half2 hk1 = __hfma2(hw00, A.h2[1], __hfma2(hw01, B.h2[1],
                      __hfma2(hw10, C.h2[1], __hmul2(hw11, D.h2[1]))));
        __half2 hv0 = __hfma2(hw00, A.h2[2], __hfma2(hw01, B.h2[2],
                      __hfma2(hw10, C.h2[2], __hmul2(hw11, D.h2[2]))));
        __half2 hv1 = __hfma2(hw00, A.h2[3], __hfma2(hw01, B.h2[3],
                      __hfma2(hw10, C.h2[3], __hmul2(hw11, D.h2[3]))));
        float2 kf0 = __half22float2(hk0), kf1 = __half22float2(hk1);
        float2 vf0 = __half22float2(hv0), vf1 = __half22float2(hv1);
        u64t aka = pk2(kf0.x, kf0.y), akb = pk2(kf1.x, kf1.y);
        u64t ava = pk2(vf0.x, vf0.y), avb = pk2(vf1.x, vf1.y);

        float2 p0 = unpk(ffma2(Q0.u[0], aka, fmul2(Q0.u[1], akb)));
        float2 p1 = unpk(ffma2(Q1.u[0], aka, fmul2(Q1.u[1], akb)));
        float2 p2 = unpk(ffma2(Q2.u[0], aka, fmul2(Q2.u[1], akb)));
        float d0 = p0.x + p0.y, d1 = p1.x + p1.y, d2 = p2.x + p2.y;
#pragma unroll
        for (int off = 8; off > 0; off >>= 1) {
            d0 += __shfl_xor_sync(0xffffffffu, d0, off);
            d1 += __shfl_xor_sync(0xffffffffu, d1, off);
            d2 += __shfl_xor_sync(0xffffffffu, d2, off);
        }
        float e0 = __expf(d0 * 0.125f);
        float e1 = __expf(d1 * 0.125f);
        float e2 = __expf(d2 * 0.125f);
        s0v += e0; s1v += e1; s2v += e2;
        u64t e0p = splat2(e0), e1p = splat2(e1), e2p = splat2(e2);
        o0a = ffma2(e0p, ava, o0a); o0b = ffma2(e0p, avb, o0b);
        o1a = ffma2(e1p, ava, o1a); o1b = ffma2(e1p, avb, o1b);
        o2a = ffma2(e2p, ava, o2a); o2b = ffma2(e2p, avb, o2b);

        T0 = N0; T1 = N1; T2 = N2; T3 = N3;
        cwx1 = nwx1; cwy1 = nwy1;
    }

    o0a = fadd2(o0a, shflx64(o0a, 16)); o0b = fadd2(o0b, shflx64(o0b, 16));
    o1a = fadd2(o1a, shflx64(o1a, 16)); o1b = fadd2(o1b, shflx64(o1b, 16));
    o2a = fadd2(o2a, shflx64(o2a, 16)); o2b = fadd2(o2b, shflx64(o2b, 16));
    s0v += __shfl_xor_sync(0xffffffffu, s0v, 16);
    s1v += __shfl_xor_sync(0xffffffffu, s1v, 16);
    s2v += __shfl_xor_sync(0xffffffffu, s2v, 16);

    if (half == 0) {
        __half* orow = g_attn + (size_t)(g * 3) * AD + h * HDIM + l * 4;
        u64t i0 = splat2(1.f / s0v), i1 = splat2(1.f / s1v), i2 = splat2(1.f / s2v);
        union { uint2 u; __half2 h2[2]; } cv;
        float2 a, b;
        a = unpk(fmul2(o0a, i0)); b = unpk(fmul2(o0b, i0));
        cv.h2[0] = __floats2half2_rn(a.x, a.y); cv.h2[1] = __floats2half2_rn(b.x, b.y);
        *(uint2*)(orow) = cv.u;
        a = unpk(fmul2(o1a, i1)); b = unpk(fmul2(o1b, i1));
        cv.h2[0] = __floats2half2_rn(a.x, a.y); cv.h2[1] = __floats2half2_rn(b.x, b.y);
        *(uint2*)(orow + AD) = cv.u;
        a = unpk(fmul2(o2a, i2)); b = unpk(fmul2(o2b, i2));
        cv.h2[0] = __floats2half2_rn(a.x, a.y); cv.h2[1] = __floats2half2_rn(b.x, b.y);
        *(uint2*)(orow + 2 * AD) = cv.u;
    }
}

// ---------------------------------------------------------------------------
// K5: out_gemm (unchanged from R7)
// ---------------------------------------------------------------------------
__global__ __launch_bounds__(256) void out_gemm(
    const float* __restrict__ Wout, const float* __restrict__ b_out,
    const float* __restrict__ feat, float* __restrict__ out)
{
    const int r0 = blockIdx.x * 64;
    __shared__ float Xs[32][66];
    __shared__ float Ws[32][32];
    const int t = threadIdx.x;
    const int c = t & 31, rb = (t >> 5) * 8;
    u64t acc2[4] = {0ull, 0ull, 0ull, 0ull};

    for (int k0 = 0; k0 < AD; k0 += 32) {
#pragma unroll
        for (int rep = 0; rep < 8; rep++) {
            int idx = t + rep * 256;
            int row = idx >> 5, kc = idx & 31;
            Xs[kc][row] = __half2float(
                g_attn[(size_t)(r0 + row) * AD + k0 + kc]);
        }
#pragma unroll
        for (int rep = 0; rep < 4; rep++) {
            int idx = t + rep * 256;
            Ws[idx >> 5][idx & 31] = Wout[(size_t)(k0 + (idx >> 5)) * GFDIM + (idx & 31)];
        }
        __syncthreads();
#pragma unroll
        for (int kk = 0; kk < 32; kk++) {
            u64t w = splat2(Ws[kk][c]);
#pragma unroll
            for (int i = 0; i < 4; i++)
                acc2[i] = ffma2(w, *(const u64t*)&Xs[kk][rb + 2 * i], acc2[i]);
        }
        __syncthreads();
    }
    float b = b_out[c];
#pragma unroll
    for (int i = 0; i < 4; i++) {
        float2 r = unpk(acc2[i]);
        int row0 = r0 + rb + 2 * i;
        out[(size_t)row0 * GFDIM + c]       = r.x + b + feat[(size_t)row0 * GFDIM + c];
        out[(size_t)(row0 + 1) * GFDIM + c] = r.y + b + feat[(size_t)(row0 + 1) * GFDIM + c];
    }
}

// ---------------------------------------------------------------------------
extern "C" void kernel_launch(void* const* d_in, const int* in_sizes, int n_in,
                              void* d_out, int out_size)
{
    const float* means      = (const float*)d_in[0];
    const float* scales     = (const float*)d_in[1];
    const float* rotations  = (const float*)d_in[2];
    const float* features   = (const float*)d_in[3];
    const float* transforms = (const float*)d_in[4];
    const float* projection = (const float*)d_in[5];
    const float* image_feat = (const float*)d_in[6];
    const float* Wq         = (const float*)d_in[7];
    const float* Wk         = (const float*)d_in[8];
    const float* Wv         = (const float*)d_in[9];
    const float* W_off      = (const float*)d_in[10];
    const float* b_off      = (const float*)d_in[11];
    const float* Wout       = (const float*)d_in[12];
    const float* b_out      = (const float*)d_in[13];
    float* out = (float*)d_out;

    kv_gemm<<<dim3(NPIX / 64, AD / 128), 256>>>(image_feat, Wk, Wv);
    q_gemm<<<dim3(G_N * 3 / 64, AD / 256), 256>>>(features, Wq);
    sigpp<<<NGH / 64, 256>>>(means, scales, rotations, transforms,
                             projection, W_off, b_off);
    gather_attn<<<G_N, 256>>>();
    out_gemm<<<G_N * 3 / 64, 256>>>(Wout, b_out, features, out);
}

// round 10
// speedup vs baseline: 1.3976x; 1.0230x over previous
#include <cuda_runtime.h>
#include <cuda_fp16.h>

#define G_N   8192
#define NH    8
#define HDIM  64
#define AD    512
#define GFDIM 32
#define CIMG  256
#define IMG   64
#define NPIX  (IMG*IMG)
#define KPTS  12
#define SIGC  9.21f
#define NGH   (G_N * NH)

typedef unsigned long long u64t;

// ---- packed f32x2 helpers ----
__device__ __forceinline__ u64t ffma2(u64t a, u64t b, u64t c) {
    u64t d; asm("fma.rn.f32x2 %0, %1, %2, %3;" : "=l"(d) : "l"(a), "l"(b), "l"(c));
    return d;
}
__device__ __forceinline__ u64t fmul2(u64t a, u64t b) {
    u64t d; asm("mul.rn.f32x2 %0, %1, %2;" : "=l"(d) : "l"(a), "l"(b)); return d;
}
__device__ __forceinline__ u64t fadd2(u64t a, u64t b) {
    u64t d; asm("add.rn.f32x2 %0, %1, %2;" : "=l"(d) : "l"(a), "l"(b)); return d;
}
__device__ __forceinline__ u64t splat2(float x) {
    u64t d; asm("mov.b64 %0, {%1, %1};" : "=l"(d) : "f"(x)); return d;
}
__device__ __forceinline__ u64t pk2(float x, float y) {
    u64t d; asm("mov.b64 %0, {%1, %2};" : "=l"(d) : "f"(x), "f"(y)); return d;
}
__device__ __forceinline__ float2 unpk(u64t a) {
    float2 r; asm("mov.b64 {%0, %1}, %2;" : "=f"(r.x), "=f"(r.y) : "l"(a)); return r;
}
__device__ __forceinline__ u64t shflx64(u64t v, int m) {
    float2 f = unpk(v);
    f.x = __shfl_xor_sync(0xffffffffu, f.x, m);
    f.y = __shfl_xor_sync(0xffffffffu, f.y, m);
    return pk2(f.x, f.y);
}

// Scratch (total ~65 MB -> L2-resident working set)
__device__ __half g_kv[NH * NPIX * 128];     // 8MB   [h][pix][lane16: k4|v4]
__device__ __half g_q[G_N * 3 * AD];         // 25MB  fp16 queries
__device__ int2   g_pts[NGH * KPTS];         // 6.3MB {pix<<4|fl, half2(wx1,wy1)}
__device__ __half g_attn[G_N * 3 * AD];      // 25MB  attention out fp16

__constant__ float c_fix[18] = {0,0,0, 1,0,0, 0,1,0, 0,0,1, -1,0,0, 0,-1,0};

// ---------------------------------------------------------------------------
// K1: kv maps -> fp16 g_kv (unchanged)
// ---------------------------------------------------------------------------
__global__ __launch_bounds__(256) void kv_gemm(
    const float* __restrict__ img, const float* __restrict__ Wk,
    const float* __restrict__ Wv)
{
    const int m0 = blockIdx.x * 64;
    const int n0 = blockIdx.y * 128;
    __shared__ float As[16][64];
    __shared__ float Bks[16][128];
    __shared__ float Bvs[16][128];
    const int t  = threadIdx.x;
    const int tx = t & 15, ty = t >> 4;

    u64t ak2[4][4], av2[4][4];
#pragma unroll
    for (int i = 0; i < 4; i++)
#pragma unroll
        for (int j = 0; j < 4; j++) { ak2[i][j] = 0ull; av2[i][j] = 0ull; }

    for (int c0 = 0; c0 < CIMG; c0 += 16) {
        *(float4*)&As[ty][tx * 4] =
            *(const float4*)(img + (size_t)(c0 + ty) * NPIX + m0 + tx * 4);
#pragma unroll
        for (int rep = 0; rep < 2; rep++) {
            int idx = t + rep * 256;
            int nn  = idx >> 2;
            int kk4 = (idx & 3) * 4;
            float4 wk = *(const float4*)(Wk + (size_t)(n0 + nn) * CIMG + c0 + kk4);
            float4 wv = *(const float4*)(Wv + (size_t)(n0 + nn) * CIMG + c0 + kk4);
            Bks[kk4 + 0][nn] = wk.x; Bks[kk4 + 1][nn] = wk.y;
            Bks[kk4 + 2][nn] = wk.z; Bks[kk4 + 3][nn] = wk.w;
            Bvs[kk4 + 0][nn] = wv.x; Bvs[kk4 + 1][nn] = wv.y;
            Bvs[kk4 + 2][nn] = wv.z; Bvs[kk4 + 3][nn] = wv.w;
        }
        __syncthreads();
#pragma unroll
        for (int kk = 0; kk < 16; kk++) {
            float4 a4 = *(float4*)&As[kk][ty * 4];
            ulonglong2 bkl = *(ulonglong2*)&Bks[kk][tx * 4];
            ulonglong2 bkh = *(ulonglong2*)&Bks[kk][tx * 4 + 64];
            ulonglong2 bvl = *(ulonglong2*)&Bvs[kk][tx * 4];
            ulonglong2 bvh = *(ulonglong2*)&Bvs[kk][tx * 4 + 64];
            u64t bk[4] = {bkl.x, bkl.y, bkh.x, bkh.y};
            u64t bv[4] = {bvl.x, bvl.y, bvh.x, bvh.y};
            float a[4] = {a4.x, a4.y, a4.z, a4.w};
#pragma unroll
            for (int i = 0; i < 4; i++) {
                u64t as = splat2(a[i]);
#pragma unroll
                for (int j = 0; j < 4; j++) {
                    ak2[i][j] = ffma2(as, bk[j], ak2[i][j]);
                    av2[i][j] = ffma2(as, bv[j], av2[i][j]);
                }
            }
        }
        __syncthreads();
    }
#pragma unroll
    for (int i = 0; i < 4; i++) {
        int m = m0 + ty * 4 + i;
#pragma unroll
        for (int q = 0; q < 2; q++) {
            int hh = (n0 >> 6) + q;
            __half* dst = g_kv + ((size_t)(hh * NPIX + m)) * 128 + tx * 8;
            float2 k0 = unpk(ak2[i][q*2+0]), k1 = unpk(ak2[i][q*2+1]);
            float2 v0 = unpk(av2[i][q*2+0]), v1 = unpk(av2[i][q*2+1]);
            union { uint4 u; __half2 h2[4]; } p;
            p.h2[0] = __floats2half2_rn(k0.x, k0.y);
            p.h2[1] = __floats2half2_rn(k1.x, k1.y);
            p.h2[2] = __floats2half2_rn(v0.x, v0.y);
            p.h2[3] = __floats2half2_rn(v1.x, v1.y);
            *(uint4*)dst = p.u;
        }
    }
}

// ---------------------------------------------------------------------------
// K2: q = features @ Wq -> fp16 g_q.  FFMA2 inner loop.
// ---------------------------------------------------------------------------
__global__ __launch_bounds__(256) void q_gemm(
    const float* __restrict__ feat, const float* __restrict__ Wq)
{
    const int r0 = blockIdx.x * 64;
    const int n0 = blockIdx.y * 256;
    __shared__ float Fs[64][32];
    __shared__ float Ws[32][256];
    const int t = threadIdx.x;
#pragma unroll
    for (int rep = 0; rep < 8; rep++) {
        int idx = t + rep * 256;
        Fs[idx >> 5][idx & 31] = feat[(size_t)(r0 + (idx >> 5)) * GFDIM + (idx & 31)];
    }
#pragma unroll
    for (int rep = 0; rep < 8; rep++) {
        int idx = t + rep * 256;
        int k = idx >> 6, n4 = (idx & 63) << 2;
        *(float4*)&Ws[k][n4] = *(const float4*)(Wq + (size_t)k * AD + n0 + n4);
    }
    __syncthreads();

    const int tc = t & 15, tr = t >> 4;
    u64t acc2[4][8];
#pragma unroll
    for (int i = 0; i < 4; i++)
#pragma unroll
        for (int j = 0; j < 8; j++) acc2[i][j] = 0ull;

#pragma unroll
    for (int k = 0; k < 32; k++) {
        u64t fs[4];
#pragma unroll
        for (int i = 0; i < 4; i++) fs[i] = splat2(Fs[tr * 4 + i][k]);
        u64t w[8];
#pragma unroll
        for (int q = 0; q < 4; q++) {
            ulonglong2 w2 = *(ulonglong2*)&Ws[k][q * 64 + tc * 4];
            w[q*2+0] = w2.x; w[q*2+1] = w2.y;
        }
#pragma unroll
        for (int i = 0; i < 4; i++)
#pragma unroll
            for (int j = 0; j < 8; j++) acc2[i][j] = ffma2(fs[i], w[j], acc2[i][j]);
    }
#pragma unroll
    for (int i = 0; i < 4; i++) {
        int r = r0 + tr * 4 + i;
#pragma unroll
        for (int q = 0; q < 4; q++) {
            float2 a = unpk(acc2[i][q*2+0]), b = unpk(acc2[i][q*2+1]);
            union { uint2 u; __half2 h2[2]; } cv;
            cv.h2[0] = __floats2half2_rn(a.x, a.y);
            cv.h2[1] = __floats2half2_rn(b.x, b.y);
            *(uint2*)&g_q[(size_t)r * AD + n0 + q * 64 + tc * 4] = cv.u;
        }
    }
}

// ---------------------------------------------------------------------------
// K3: sigpp — fused OffsetNet GEMM + point projection -> packed int2 g_pts.
// ---------------------------------------------------------------------------
__global__ __launch_bounds__(256) void sigpp(
    const float* __restrict__ means, const float* __restrict__ scales,
    const float* __restrict__ rots, const float* __restrict__ transforms,
    const float* __restrict__ proj, const float* __restrict__ W_off,
    const float* __restrict__ b_off)
{
    const int r0 = blockIdx.x * 64;
    __shared__ float Xs[64][69];
    __shared__ float Ws[67][20];
    __shared__ float bs[20];
    __shared__ float sh_learn[64][18];
    __shared__ float sh_rot[8][9];
    __shared__ float sh_scl[8][3];
    __shared__ float sh_proj[12];
    const int t = threadIdx.x;

    for (int idx = t; idx < 64 * 64; idx += 256) {
        int rl = idx >> 6, c = idx & 63;
        int r = r0 + rl, g = r >> 3, h = r & 7;
        const __half* q = g_q + (size_t)(g * 3) * AD + h * HDIM + c;
        Xs[rl][3 + c] = (__half2float(q[0]) + __half2float(q[AD])
                       + __half2float(q[2 * AD])) * (1.f / 3.f);
    }
    if (t < 64) {
        int r = r0 + t, g = r >> 3;
        float mx = means[g*3], my = means[g*3+1], mz = means[g*3+2];
        const float* T = transforms + (size_t)g * 16;
        Xs[t][0] = T[0]*mx + T[1]*my + T[2] *mz + T[3];
        Xs[t][1] = T[4]*mx + T[5]*my + T[6] *mz + T[7];
        Xs[t][2] = T[8]*mx + T[9]*my + T[10]*mz + T[11];
    }
    for (int idx = t; idx < 67 * 20; idx += 256) {
        int i = idx / 20, o = idx % 20;
        Ws[i][o] = (o < 18) ? W_off[i * 18 + o] : 0.f;
    }
    if (t < 20) bs[t] = (t < 18) ? b_off[t] : 0.f;
    if (t < 12) sh_proj[t] = proj[t];
    if (t >= 32 && t < 40) {
        int gl = t - 32, g = (r0 >> 3) + gl;
        float qw = rots[g*4+0], qx = rots[g*4+1], qy = rots[g*4+2], qz = rots[g*4+3];
        float qn = rsqrtf(qw*qw + qx*qx + qy*qy + qz*qz);
        qw *= qn; qx *= qn; qy *= qn; qz *= qn;
        sh_rot[gl][0] = 1.f-2.f*(qy*qy+qz*qz); sh_rot[gl][1] = 2.f*(qx*qy-qw*qz);
        sh_rot[gl][2] = 2.f*(qx*qz+qw*qy);     sh_rot[gl][3] = 2.f*(qx*qy+qw*qz);
        sh_rot[gl][4] = 1.f-2.f*(qx*qx+qz*qz); sh_rot[gl][5] = 2.f*(qy*qz-qw*qx);
        sh_rot[gl][6] = 2.f*(qx*qz-qw*qy);     sh_rot[gl][7] = 2.f*(qy*qz+qw*qx);
        sh_rot[gl][8] = 1.f-2.f*(qx*qx+qy*qy);
        sh_scl[gl][0] = scales[g*3+0];
        sh_scl[gl][1] = scales[g*3+1];
        sh_scl[gl][2] = scales[g*3+2];
    }
    __syncthreads();

    {
        const int rl = t & 63, og = t >> 6;
        const int obase = og * 5;
        float acc[5] = {0.f, 0.f, 0.f, 0.f, 0.f};
        for (int i = 0; i < 67; i++) {
            float x = Xs[rl][i];
#pragma unroll
            for (int u = 0; u < 5; u++) acc[u] += x * Ws[i][obase + u];
        }
        const int on = (og == 3) ? 3 : 5;
        for (int u = 0; u < on; u++) {
            float z = acc[u] + bs[obase + u];
            z = fminf(fmaxf(z, -SIGC), SIGC);
            sh_learn[rl][obase + u] = 1.f / (1.f + __expf(-z)) - 0.5f;
        }
    }
    __syncthreads();

#pragma unroll
    for (int it = 0; it < 3; it++) {
        int id = t + it * 256;
        int rl = id / KPTS, kp = id - rl * KPTS;
        int gl = rl >> 3;
        float s0, s1, s2;
        if (kp < 6) { s0 = c_fix[kp*3+0]; s1 = c_fix[kp*3+1]; s2 = c_fix[kp*3+2]; }
        else { const float* lp = &sh_learn[rl][(kp - 6) * 3];
               s0 = lp[0]; s1 = lp[1]; s2 = lp[2]; }
        float v0 = s0 * sh_scl[gl][0], v1 = s1 * sh_scl[gl][1], v2 = s2 * sh_scl[gl][2];
        const float* R = sh_rot[gl];
        float px = R[0]*v0 + R[3]*v1 + R[6]*v2 + Xs[rl][0];
        float py = R[1]*v0 + R[4]*v1 + R[7]*v2 + Xs[rl][1];
        float pz = R[2]*v0 + R[5]*v1 + R[8]*v2 + Xs[rl][2];
        float p0 = sh_proj[0]*px + sh_proj[1]*py + sh_proj[2] *pz + sh_proj[3];
        float p1 = sh_proj[4]*px + sh_proj[5]*py + sh_proj[6] *pz + sh_proj[7];
        float p2 = sh_proj[8]*px + sh_proj[9]*py + sh_proj[10]*pz + sh_proj[11];
        float zz = fmaxf(p2, 1e-5f);
        float u = p0 / zz, v = p1 / zz;
        const float lim = 0.9999f * (float)IMG;
        float xf = fminf(fmaxf(u, 0.f), lim) - 0.5f;
        float yf = fminf(fmaxf(v, 0.f), lim) - 0.5f;
        float fx0 = floorf(xf), fy0 = floorf(yf);
        float wx1 = xf - fx0, wy1 = yf - fy0;
        int x0 = (int)fx0, y0 = (int)fy0;
        int pix = y0 * IMG + x0;                 // signed pixel index
        int vx0 = (unsigned)x0       < IMG;
        int vx1 = (unsigned)(x0 + 1) < IMG;
        int vy0 = (unsigned)y0       < IMG;
        int vy1 = (unsigned)(y0 + 1) < IMG;
        int fl = (vy0 & vx0) | ((vy0 & vx1) << 1) | ((vy1 & vx0) << 2) | ((vy1 & vx1) << 3);
        union { __half2 h; int i; } wv;
        wv.h = __floats2half2_rn(wx1, wy1);
        g_pts[(size_t)(r0 + rl) * KPTS + kp] = make_int2((pix << 4) | fl, wv.i);
    }
}

// ---------------------------------------------------------------------------
// K4: gather_attn — fp16 q, packed int2 points.
// ---------------------------------------------------------------------------
__global__ __launch_bounds__(256) void gather_attn()
{
    const int g    = blockIdx.x;
    const int tid  = threadIdx.x;
    const int h    = tid >> 5;
    const int lane = tid & 31;
    const int l    = lane & 15;
    const int half = lane >> 4;

    // q channels 4l..4l+3 per token, fp16 -> packed f32x2 pairs
    const __half* qr = g_q + (size_t)(g * 3) * AD + h * HDIM + l * 4;
    u64t Q0a, Q0b, Q1a, Q1b, Q2a, Q2b;
    {
        union { uint2 u; __half2 h2[2]; } c;
        float2 a, b;
        c.u = *(const uint2*)(qr);
        a = __half22float2(c.h2[0]); b = __half22float2(c.h2[1]);
        Q0a = pk2(a.x, a.y); Q0b = pk2(b.x, b.y);
        c.u = *(const uint2*)(qr + AD);
        a = __half22float2(c.h2[0]); b = __half22float2(c.h2[1]);
        Q1a = pk2(a.x, a.y); Q1b = pk2(b.x, b.y);
        c.u = *(const uint2*)(qr + 2 * AD);
        a = __half22float2(c.h2[0]); b = __half22float2(c.h2[1]);
        Q2a = pk2(a.x, a.y); Q2b = pk2(b.x, b.y);
    }

    int2 pt;
    { int kpl = lane < KPTS ? lane : KPTS - 1;
      pt = g_pts[(size_t)(g * NH + h) * KPTS + kpl]; }

    const char* kvb = (const char*)g_kv + (size_t)h * NPIX * 256 + l * 16;

    float s0v = 0.f, s1v = 0.f, s2v = 0.f;
    u64t o0a = 0ull, o0b = 0ull, o1a = 0ull, o1b = 0ull, o2a = 0ull, o2b = 0ull;

    uint4 T0, T1, T2, T3;
    float cwx1, cwy1;
    int cfl;
    {
        int w0 = __shfl_sync(0xffffffffu, pt.x, half);
        int w1 = __shfl_sync(0xffffffffu, pt.y, half);
        cfl = w0 & 15;
        union { int i; __half2 h; } wu; wu.i = w1;
        float2 w = __half22float2(wu.h);
        cwx1 = w.x; cwy1 = w.y;
        const char* p = kvb + ((long)(w0 >> 4) << 8);
        T0 = T1 = T2 = T3 = make_uint4(0, 0, 0, 0);
        if (cfl & 1) T0 = *(const uint4*)(p);
        if (cfl & 2) T1 = *(const uint4*)(p + 256);
        if (cfl & 4) T2 = *(const uint4*)(p + IMG * 256);
        if (cfl & 8) T3 = *(const uint4*)(p + IMG * 256 + 256);
    }

#pragma unroll
    for (int i = 0; i < KPTS / 2; i++) {
        uint4 N0, N1, N2, N3;
        float nwx1 = 0.f, nwy1 = 0.f;
        N0 = N1 = N2 = N3 = make_uint4(0, 0, 0, 0);
        if (i < KPTS / 2 - 1) {
            int src = 2 * (i + 1) + half;
            int w0 = __shfl_sync(0xffffffffu, pt.x, src);
            int w1 = __shfl_sync(0xffffffffu, pt.y, src);
            int bf = w0 & 15;
            union { int i; __half2 h; } wu; wu.i = w1;
            float2 w = __half22float2(wu.h);
            nwx1 = w.x; nwy1 = w.y;
            const char* p = kvb + ((long)(w0 >> 4) << 8);
            if (bf & 1) N0 = *(const uint4*)(p);
            if (bf & 2) N1 = *(const uint4*)(p + 256);
            if (bf & 4) N2 = *(const uint4*)(p + IMG * 256);
            if (bf & 8) N3 = *(const uint4*)(p + IMG * 256 + 256);
        }

        float wx0 = 1.f - cwx1, wy0 = 1.f - cwy1;
        __half2 hw00 = __float2half2_rn(wx0  * wy0);
        __half2 hw01 = __float2half2_rn(cwx1 * wy0);
        __half2 hw10 = __float2half2_rn(wx0  * cwy1);
        __half2 hw11 = __float2half2_rn(cwx1 * cwy1);
        union { uint4 u; __half2 h2[4]; } A, B, C, D;
        A.u = T0; B.u = T1; C.u = T2; D.u = T3;
        __half2 hk0 = __hfma2(hw00, A.h2[0], __hfma2(hw01, B.h2[0],
                      __hfma2(hw10, C.h2[0], __hmul2(hw11, D.h2[0]))));
        __half2 hk1 = __hfma2(hw00, A.h2[1], __hfma2(hw01, B.h2[1],
                      __hfma2(hw10, C.h2[1], __hmul2(hw11, D.h2[1]))));
        __half2 hv0 = __hfma2(hw00, A.h2[2], __hfma2(hw01, B.h2[2],
                      __hfma2(hw10, C.h2[2], __hmul2(hw11, D.h2[2]))));
        __half2 hv1 = __hfma2(hw00, A.h2[3], __hfma2(hw01, B.h2[3],
                      __hfma2(hw10, C.h2[3], __hmul2(hw11, D.h2[3]))));
        float2 kf0 = __half22float2(hk0), kf1 = __half22float2(hk1);
        float2 vf0 = __half22float2(hv0), vf1 = __half22float2(hv1);
        u64t aka = pk2(kf0.x, kf0.y), akb = pk2(kf1.x, kf1.y);
        u64t ava = pk2(vf0.x, vf0.y), avb = pk2(vf1.x, vf1.y);

        float2 p0 = unpk(ffma2(Q0a, aka, fmul2(Q0b, akb)));
        float2 p1 = unpk(ffma2(Q1a, aka, fmul2(Q1b, akb)));
        float2 p2 = unpk(ffma2(Q2a, aka, fmul2(Q2b, akb)));
        float d0 = p0.x + p0.y, d1 = p1.x + p1.y, d2 = p2.x + p2.y;
#pragma unroll
        for (int off = 8; off > 0; off >>= 1) {
            d0 += __shfl_xor_sync(0xffffffffu, d0, off);
            d1 += __shfl_xor_sync(0xffffffffu, d1, off);
            d2 += __shfl_xor_sync(0xffffffffu, d2, off);
        }
        float e0 = __expf(d0 * 0.125f);
        float e1 = __expf(d1 * 0.125f);
        float e2 = __expf(d2 * 0.125f);
        s0v += e0; s1v += e1; s2v += e2;
        u64t e0p = splat2(e0), e1p = splat2(e1), e2p = splat2(e2);
        o0a = ffma2(e0p, ava, o0a); o0b = ffma2(e0p, avb, o0b);
        o1a = ffma2(e1p, ava, o1a); o1b = ffma2(e1p, avb, o1b);
        o2a = ffma2(e2p, ava, o2a); o2b = ffma2(e2p, avb, o2b);

        T0 = N0; T1 = N1; T2 = N2; T3 = N3;
        cwx1 = nwx1; cwy1 = nwy1;
    }

    o0a = fadd2(o0a, shflx64(o0a, 16)); o0b = fadd2(o0b, shflx64(o0b, 16));
    o1a = fadd2(o1a, shflx64(o1a, 16)); o1b = fadd2(o1b, shflx64(o1b, 16));
    o2a = fadd2(o2a, shflx64(o2a, 16)); o2b = fadd2(o2b, shflx64(o2b, 16));
    s0v += __shfl_xor_sync(0xffffffffu, s0v, 16);
    s1v += __shfl_xor_sync(0xffffffffu, s1v, 16);
    s2v += __shfl_xor_sync(0xffffffffu, s2v, 16);

    if (half == 0) {
        __half* orow = g_attn + (size_t)(g * 3) * AD + h * HDIM + l * 4;
        u64t i0 = splat2(1.f / s0v), i1 = splat2(1.f / s1v), i2 = splat2(1.f / s2v);
        union { uint2 u; __half2 h2[2]; } cv;
        float2 a, b;
        a = unpk(fmul2(o0a, i0)); b = unpk(fmul2(o0b, i0));
        cv.h2[0] = __floats2half2_rn(a.x, a.y); cv.h2[1] = __floats2half2_rn(b.x, b.y);
        *(uint2*)(orow) = cv.u;
        a = unpk(fmul2(o1a, i1)); b = unpk(fmul2(o1b, i1));
        cv.h2[0] = __floats2half2_rn(a.x, a.y); cv.h2[1] = __floats2half2_rn(b.x, b.y);
        *(uint2*)(orow + AD) = cv.u;
        a = unpk(fmul2(o2a, i2)); b = unpk(fmul2(o2b, i2));
        cv.h2[0] = __floats2half2_rn(a.x, a.y); cv.h2[1] = __floats2half2_rn(b.x, b.y);
        *(uint2*)(orow + 2 * AD) = cv.u;
    }
}

// ---------------------------------------------------------------------------
// K5: out_gemm (unchanged)
// ---------------------------------------------------------------------------
__global__ __launch_bounds__(256) void out_gemm(
    const float* __restrict__ Wout, const float* __restrict__ b_out,
    const float* __restrict__ feat, float* __restrict__ out)
{
    const int r0 = blockIdx.x * 64;
    __shared__ float Xs[32][66];
    __shared__ float Ws[32][32];
    const int t = threadIdx.x;
    const int c = t & 31, rb = (t >> 5) * 8;
    u64t acc2[4] = {0ull, 0ull, 0ull, 0ull};

    for (int k0 = 0; k0 < AD; k0 += 32) {
#pragma unroll
        for (int rep = 0; rep < 8; rep++) {
            int idx = t + rep * 256;
            int row = idx >> 5, kc = idx & 31;
            Xs[kc][row] = __half2float(
                g_attn[(size_t)(r0 + row) * AD + k0 + kc]);
        }
#pragma unroll
        for (int rep = 0; rep < 4; rep++) {
            int idx = t + rep * 256;
            Ws[idx >> 5][idx & 31] = Wout[(size_t)(k0 + (idx >> 5)) * GFDIM + (idx & 31)];
        }
        __syncthreads();
#pragma unroll
        for (int kk = 0; kk < 32; kk++) {
            u64t w = splat2(Ws[kk][c]);
#pragma unroll
            for (int i = 0; i < 4; i++)
                acc2[i] = ffma2(w, *(const u64t*)&Xs[kk][rb + 2 * i], acc2[i]);
        }
        __syncthreads();
    }
    float b = b_out[c];
#pragma unroll
    for (int i = 0; i < 4; i++) {
        float2 r = unpk(acc2[i]);
        int row0 = r0 + rb + 2 * i;
        out[(size_t)row0 * GFDIM + c]       = r.x + b + feat[(size_t)row0 * GFDIM + c];
        out[(size_t)(row0 + 1) * GFDIM + c] = r.y + b + feat[(size_t)(row0 + 1) * GFDIM + c];
    }
}

// ---------------------------------------------------------------------------
extern "C" void kernel_launch(void* const* d_in, const int* in_sizes, int n_in,
                              void* d_out, int out_size)
{
    const float* means      = (const float*)d_in[0];
    const float* scales     = (const float*)d_in[1];
    const float* rotations  = (const float*)d_in[2];
    const float* features   = (const float*)d_in[3];
    const float* transforms = (const float*)d_in[4];
    const float* projection = (const float*)d_in[5];
    const float* image_feat = (const float*)d_in[6];
    const float* Wq         = (const float*)d_in[7];
    const float* Wk         = (const float*)d_in[8];
    const float* Wv         = (const float*)d_in[9];
    const float* W_off      = (const float*)d_in[10];
    const float* b_off      = (const float*)d_in[11];
    const float* Wout       = (const float*)d_in[12];
    const float* b_out      = (const float*)d_in[13];
    float* out = (float*)d_out;

    kv_gemm<<<dim3(NPIX / 64, AD / 128), 256>>>(image_feat, Wk, Wv);
    q_gemm<<<dim3(G_N * 3 / 64, AD / 256), 256>>>(features, Wq);
    sigpp<<<NGH / 64, 256>>>(means, scales, rotations, transforms,
                             projection, W_off, b_off);
    gather_attn<<<G_N, 256>>>();
    out_gemm<<<G_N * 3 / 64, 256>>>(Wout, b_out, features, out);
}